// round 8
// baseline (speedup 1.0000x reference)
#include <cuda_runtime.h>
#include <cuda_fp16.h>
#include <cstdint>

#define NROWS 8192
#define CH    512
#define NC    ((size_t)NROWS * CH)          // 4,194,304
#define S_ELEMS ((size_t)NROWS * NROWS)     // 67,108,864

// float region: a1,a2,attn1,attn2 (4*NC)
// half  region: sph,om1h,om2h,qh,k1h,k2h,vh,vTh (8*NC), S1,S2,P1,P2 (4*S_ELEMS), weights
#define FLOAT_REGION (4 * NC)
#define HALF_REGION  (8 * NC + 4 * S_ELEMS + 2097152)
__device__ float g_scratch[FLOAT_REGION + HALF_REGION / 2 + 1024];

// ===========================================================================
// helpers
// ===========================================================================
__device__ __forceinline__ uint32_t smem_u32(const void* p) {
    uint32_t a;
    asm("{ .reg .u64 t; cvta.to.shared.u64 t, %1; cvt.u32.u64 %0, t; }"
        : "=r"(a) : "l"(p));
    return a;
}
__device__ __forceinline__ void cp16(uint32_t dst, const void* src) {
    asm volatile("cp.async.cg.shared.global [%0], [%1], 16;" :: "r"(dst), "l"(src));
}
__device__ __forceinline__ void ldmx4(uint32_t* r, uint32_t addr) {
    asm volatile("ldmatrix.sync.aligned.m8n8.x4.shared.b16 {%0,%1,%2,%3}, [%4];"
                 : "=r"(r[0]), "=r"(r[1]), "=r"(r[2]), "=r"(r[3]) : "r"(addr));
}
__device__ __forceinline__ void mma_f16(float* d, const uint32_t* a,
                                        uint32_t b0, uint32_t b1) {
    asm volatile(
        "mma.sync.aligned.m16n8k16.row.col.f32.f16.f16.f32 "
        "{%0,%1,%2,%3}, {%4,%5,%6,%7}, {%8,%9}, {%0,%1,%2,%3};"
        : "+f"(d[0]), "+f"(d[1]), "+f"(d[2]), "+f"(d[3])
        : "r"(a[0]), "r"(a[1]), "r"(a[2]), "r"(a[3]), "r"(b0), "r"(b1));
}
// 16B-chunk swizzle within a 64B row -> conflict-free ldmatrix + cp.async
__device__ __forceinline__ uint32_t sw16(int r, int c) {
    return (uint32_t)((c ^ ((r >> 1) & 3)) * 16);
}

// ===========================================================================
// fp16 NT GEMM, tile 128x64, 128 threads (4 warps in m), 4 CTAs/SM.
// grid.z batching via alternate pointers (blockIdx.z==1 swaps non-null alts).
//   A: fp16 K-major, optionally 3-seg K-concat (seg len = 1<<seg_shift)
//   B: fp16 [Nfull, K] row-major
// Per-warp tile 32x64 (identical microkernel to the proven R5 inner loop).
// ===========================================================================
#define STAGES   4
#define A_TILE_B 8192                  // 128 rows * 64B
#define B_TILE_B 4096                  // 64 rows * 64B
#define STAGE_B  12288
#define SMEM_GEMM (STAGES * STAGE_B)   // 49152

template <typename OutT>
__global__ void __launch_bounds__(128, 4)
mma_nt_kernel(OutT* C, const __half* A0, const __half* A1, const __half* A2,
              const __half* B, const float* bias,
              OutT* Cb, const __half* A0b, const __half* A1b, const __half* Bb,
              int Nfull, int K, int seg_shift, float scale)
{
    if (blockIdx.z == 1) {
        if (Cb)  C  = Cb;
        if (A0b) A0 = A0b;
        if (A1b) A1 = A1b;
        if (Bb)  B  = Bb;
    }
    extern __shared__ char sm[];
    const uint32_t sbase = smem_u32(sm);
    const int tid  = threadIdx.x;
    const int warp = tid >> 5;           // 0..3 (m only)
    const int lane = tid & 31;
    const int m0   = blockIdx.y * 128;
    const int n0   = blockIdx.x * 64;
    const int nch  = K >> 5;
    const int segmask = (1 << seg_shift) - 1;

    const int brow = tid >> 1;           // B loader row 0..63
    const int bc0  = (tid & 1) * 2;      // B loader chunk base

    auto issue = [&](int c) {
        const int kb  = c << 5;
        const int seg = kb >> seg_shift;
        const __half* Asrc = (seg == 0) ? A0 : ((seg == 1) ? A1 : A2);
        const __half* ap = Asrc + (((size_t)(m0 + tid)) << seg_shift) + (kb & segmask);
        const __half* bp = B + (size_t)(n0 + brow) * K + kb;
        const uint32_t st  = sbase + (c % STAGES) * STAGE_B;
        const uint32_t sta = st + tid * 64;
        const uint32_t stb = st + A_TILE_B + brow * 64;
#pragma unroll
        for (int ch = 0; ch < 4; ch++)
            cp16(sta + sw16(tid, ch), ap + ch * 8);
#pragma unroll
        for (int j = 0; j < 2; j++) {
            const int ch = bc0 + j;
            cp16(stb + sw16(brow, ch), bp + ch * 8);
        }
        asm volatile("cp.async.commit_group;" ::: "memory");
    };

    float acc[2][8][4];
#pragma unroll
    for (int mt = 0; mt < 2; mt++)
#pragma unroll
        for (int nt = 0; nt < 8; nt++)
#pragma unroll
            for (int r = 0; r < 4; r++) acc[mt][nt][r] = 0.0f;

    issue(0); issue(1); issue(2);

    const int l15 = lane & 15;
    const int lhi = lane >> 4;
    uint32_t aoff[2][2], boff[4][2];
#pragma unroll
    for (int mt = 0; mt < 2; mt++)
#pragma unroll
        for (int ks = 0; ks < 2; ks++) {
            const int r = warp * 32 + mt * 16 + l15;
            aoff[mt][ks] = (uint32_t)r * 64 + sw16(r, 2 * ks + lhi);
        }
#pragma unroll
    for (int np = 0; np < 4; np++)
#pragma unroll
        for (int ks = 0; ks < 2; ks++) {
            const int r = np * 16 + l15;
            boff[np][ks] = A_TILE_B + (uint32_t)r * 64 + sw16(r, 2 * ks + lhi);
        }

    for (int c = 0; c < nch; c++) {
        asm volatile("cp.async.wait_group %0;" :: "n"(2) : "memory");
        __syncthreads();
        if (c + 3 < nch) issue(c + 3);
        else asm volatile("cp.async.commit_group;" ::: "memory");

        const uint32_t st = sbase + (c % STAGES) * STAGE_B;

        uint32_t af0[2][4], af1[2][4], bf[4][4];
        ldmx4(af0[0], st + aoff[0][0]);
        ldmx4(af0[1], st + aoff[1][0]);
        ldmx4(af1[0], st + aoff[0][1]);
        ldmx4(af1[1], st + aoff[1][1]);
#pragma unroll
        for (int np = 0; np < 4; np++) ldmx4(bf[np], st + boff[np][0]);
#pragma unroll
        for (int mt = 0; mt < 2; mt++)
#pragma unroll
            for (int np = 0; np < 4; np++) {
                mma_f16(acc[mt][2 * np],     af0[mt], bf[np][0], bf[np][2]);
                mma_f16(acc[mt][2 * np + 1], af0[mt], bf[np][1], bf[np][3]);
            }
#pragma unroll
        for (int np = 0; np < 4; np++) ldmx4(bf[np], st + boff[np][1]);
#pragma unroll
        for (int mt = 0; mt < 2; mt++)
#pragma unroll
            for (int np = 0; np < 4; np++) {
                mma_f16(acc[mt][2 * np],     af1[mt], bf[np][0], bf[np][2]);
                mma_f16(acc[mt][2 * np + 1], af1[mt], bf[np][1], bf[np][3]);
            }
    }

    const int frow = lane >> 2;
    const int fcol = lane & 3;
#pragma unroll
    for (int mt = 0; mt < 2; mt++) {
        const int row = m0 + warp * 32 + mt * 16 + frow;
#pragma unroll
        for (int nt = 0; nt < 8; nt++) {
            const int col = n0 + nt * 8 + fcol * 2;
            float b0 = 0.0f, b1 = 0.0f;
            if (bias != nullptr) { b0 = bias[col]; b1 = bias[col + 1]; }
            float x0 = acc[mt][nt][0] * scale + b0;
            float x1 = acc[mt][nt][1] * scale + b1;
            float x2 = acc[mt][nt][2] * scale + b0;
            float x3 = acc[mt][nt][3] * scale + b1;
            if constexpr (sizeof(OutT) == 2) {
                *(__half2*)((__half*)C + (size_t)row * Nfull + col) =
                    __floats2half2_rn(x0, x1);
                *(__half2*)((__half*)C + (size_t)(row + 8) * Nfull + col) =
                    __floats2half2_rn(x2, x3);
            } else {
                *(float2*)((float*)C + (size_t)row * Nfull + col) = make_float2(x0, x1);
                *(float2*)((float*)C + (size_t)(row + 8) * Nfull + col) = make_float2(x2, x3);
            }
        }
    }
}

// ===========================================================================
// Fused fp32->fp16 conversion for all 8 operands
// ===========================================================================
#define SEG_IN  ((int)(NC / 4))
#define SEG_W5  65536
#define SEG_VW  196608
#define SEG_CW  131072
#define CVT_TOTAL (3 * SEG_IN + 3 * SEG_W5 + SEG_VW + SEG_CW)

__global__ void __launch_bounds__(256)
convert_all_kernel(const float* __restrict__ sp, const float* __restrict__ om1,
                   const float* __restrict__ om2, const float* __restrict__ qw,
                   const float* __restrict__ k1w, const float* __restrict__ k2w,
                   const float* __restrict__ vw, const float* __restrict__ cw,
                   __half* __restrict__ sph, __half* __restrict__ om1h,
                   __half* __restrict__ om2h, __half* __restrict__ qwh,
                   __half* __restrict__ k1wh, __half* __restrict__ k2wh,
                   __half* __restrict__ vwh, __half* __restrict__ cwh)
{
    int i = blockIdx.x * 256 + threadIdx.x;
    if (i >= CVT_TOTAL) return;
    const float* src; __half* dst; int off = i;
    if (off < SEG_IN) { src = sp; dst = sph; }
    else if ((off -= SEG_IN) < SEG_IN) { src = om1; dst = om1h; }
    else if ((off -= SEG_IN) < SEG_IN) { src = om2; dst = om2h; }
    else if ((off -= SEG_IN) < SEG_W5) { src = qw; dst = qwh; }
    else if ((off -= SEG_W5) < SEG_W5) { src = k1w; dst = k1wh; }
    else if ((off -= SEG_W5) < SEG_W5) { src = k2w; dst = k2wh; }
    else if ((off -= SEG_W5) < SEG_VW) { src = vw; dst = vwh; }
    else { off -= SEG_VW; src = cw; dst = cwh; }
    float4 x = ((const float4*)src)[off];
    ((__half2*)dst)[2 * off]     = __floats2half2_rn(x.x, x.y);
    ((__half2*)dst)[2 * off + 1] = __floats2half2_rn(x.z, x.w);
}

__global__ void __launch_bounds__(256)
transpose_h_kernel(__half* __restrict__ out, const __half* __restrict__ in)
{
    __shared__ __half tile[32][34];
    const int tx = threadIdx.x & 31;
    const int ty = threadIdx.x >> 5;
    const int x0 = blockIdx.x * 32;
    const int y0 = blockIdx.y * 32;
#pragma unroll
    for (int j = 0; j < 32; j += 8)
        tile[ty + j][tx] = in[(size_t)(y0 + ty + j) * CH + x0 + tx];
    __syncthreads();
#pragma unroll
    for (int j = 0; j < 32; j += 8)
        out[(size_t)(x0 + ty + j) * NROWS + y0 + tx] = tile[tx][ty + j];
}

// ===========================================================================
// Row softmax over 8192 cols, fp16 in / fp16 out, batched over 2 matrices
// via blockIdx.y. Math in fp32.
// ===========================================================================
__global__ void __launch_bounds__(256)
softmax_kernel(const __half* __restrict__ S1, const __half* __restrict__ S2,
               __half* __restrict__ P1, __half* __restrict__ P2)
{
    const int tid = threadIdx.x;
    const size_t roff = (size_t)blockIdx.x * NROWS;
    const uint4* pr = (const uint4*)((blockIdx.y ? S2 : S1) + roff);
    uint4* po = (uint4*)((blockIdx.y ? P2 : P1) + roff);
    __shared__ float red1[8];
    __shared__ float red2[8];

    float v[32];
#pragma unroll
    for (int i = 0; i < 4; i++) {
        uint4 u = pr[i * 256 + tid];
        float2 f;
        f = __half22float2(*(__half2*)&u.x); v[i*8+0] = f.x; v[i*8+1] = f.y;
        f = __half22float2(*((__half2*)&u.x + 1)); v[i*8+2] = f.x; v[i*8+3] = f.y;
        f = __half22float2(*(__half2*)&u.z); v[i*8+4] = f.x; v[i*8+5] = f.y;
        f = __half22float2(*((__half2*)&u.z + 1)); v[i*8+6] = f.x; v[i*8+7] = f.y;
    }

    float m = -3.0e38f;
#pragma unroll
    for (int j = 0; j < 32; j++) m = fmaxf(m, v[j]);
#pragma unroll
    for (int o = 16; o > 0; o >>= 1)
        m = fmaxf(m, __shfl_xor_sync(0xffffffff, m, o));
    if ((tid & 31) == 0) red1[tid >> 5] = m;
    __syncthreads();
    m = red1[0];
#pragma unroll
    for (int i = 1; i < 8; i++) m = fmaxf(m, red1[i]);

    float s = 0.0f;
#pragma unroll
    for (int j = 0; j < 32; j++) { v[j] = __expf(v[j] - m); s += v[j]; }
#pragma unroll
    for (int o = 16; o > 0; o >>= 1)
        s += __shfl_xor_sync(0xffffffff, s, o);
    if ((tid & 31) == 0) red2[tid >> 5] = s;
    __syncthreads();
    s = 0.0f;
#pragma unroll
    for (int i = 0; i < 8; i++) s += red2[i];
    const float inv = 1.0f / s;

#pragma unroll
    for (int i = 0; i < 4; i++) {
        uint4 u;
        *(__half2*)&u.x       = __floats2half2_rn(v[i*8+0] * inv, v[i*8+1] * inv);
        *((__half2*)&u.x + 1) = __floats2half2_rn(v[i*8+2] * inv, v[i*8+3] * inv);
        *(__half2*)&u.z       = __floats2half2_rn(v[i*8+4] * inv, v[i*8+5] * inv);
        *((__half2*)&u.z + 1) = __floats2half2_rn(v[i*8+6] * inv, v[i*8+7] * inv);
        po[i * 256 + tid] = u;
    }
}

// fused gate + combine: g = sigmoid(sigmoid(a1)-sigmoid(a2));
// out = g*attn1 + (1-g)*attn2
__global__ void __launch_bounds__(256)
combine_kernel(float* __restrict__ out, const float* __restrict__ a1,
               const float* __restrict__ a2, const float* __restrict__ A1,
               const float* __restrict__ A2, int n)
{
    int i = blockIdx.x * 256 + threadIdx.x;
    if (i < n) {
        float s1 = 1.0f / (1.0f + __expf(-a1[i]));
        float s2 = 1.0f / (1.0f + __expf(-a2[i]));
        float g  = 1.0f / (1.0f + __expf(-(s1 - s2)));
        out[i] = g * A1[i] + (1.0f - g) * A2[i];
    }
}

// ===========================================================================
extern "C" void kernel_launch(void* const* d_in, const int* in_sizes, int n_in,
                              void* d_out, int out_size)
{
    const float* sp   = (const float*)d_in[0];
    const float* om1  = (const float*)d_in[1];
    const float* om2  = (const float*)d_in[2];
    const float* q_w  = (const float*)d_in[3];
    const float* q_b  = (const float*)d_in[4];
    const float* k1_w = (const float*)d_in[5];
    const float* k1_b = (const float*)d_in[6];
    const float* k2_w = (const float*)d_in[7];
    const float* k2_b = (const float*)d_in[8];
    const float* v_w  = (const float*)d_in[9];
    const float* v_b  = (const float*)d_in[10];
    const float* c1_w = (const float*)d_in[11];
    const float* c1_b = (const float*)d_in[12];
    float* out = (float*)d_out;

    float* base = nullptr;
    cudaGetSymbolAddress((void**)&base, g_scratch);
    float* a1    = base + 0 * NC;
    float* a2    = base + 1 * NC;
    float* attn1 = base + 2 * NC;
    float* attn2 = base + 3 * NC;
    __half* hb   = (__half*)(base + FLOAT_REGION);
    __half* sph  = hb + 0 * NC;
    __half* om1h = hb + 1 * NC;
    __half* om2h = hb + 2 * NC;
    __half* qh   = hb + 3 * NC;
    __half* k1h  = hb + 4 * NC;
    __half* k2h  = hb + 5 * NC;
    __half* vh   = hb + 6 * NC;
    __half* vTh  = hb + 7 * NC;
    __half* S1   = hb + 8 * NC;
    __half* S2   = S1 + S_ELEMS;
    __half* P1   = S2 + S_ELEMS;
    __half* P2   = P1 + S_ELEMS;
    __half* wts  = P2 + S_ELEMS;
    __half* qwh  = wts;
    __half* k1wh = wts + 262144;
    __half* k2wh = wts + 524288;
    __half* vwh  = wts + 786432;
    __half* c1wh = wts + 1572864;

    cudaFuncSetAttribute(mma_nt_kernel<float>,
                         cudaFuncAttributeMaxDynamicSharedMemorySize, SMEM_GEMM);
    cudaFuncSetAttribute(mma_nt_kernel<__half>,
                         cudaFuncAttributeMaxDynamicSharedMemorySize, SMEM_GEMM);

    const float scale = 0.044194173824159223f;  // 1/sqrt(512)
    const int elemBlocks = (int)((NC + 255) / 256);
    typedef __half H;

    auto gemm1 = [&](auto* C, const H* A0, const H* A1p, const H* A2p,
                     const H* B, const float* bias, int M, int Nfull, int K,
                     int seg_shift, float sc) {
        using T = typename std::remove_pointer<decltype(C)>::type;
        dim3 g(Nfull / 64, M / 128, 1);
        mma_nt_kernel<T><<<g, 128, SMEM_GEMM>>>(C, A0, A1p, A2p, B, bias,
                                                (T*)nullptr, nullptr, nullptr, nullptr,
                                                Nfull, K, seg_shift, sc);
    };
    auto gemm2 = [&](auto* C, const H* A0, const H* A1p, const H* A2p,
                     const H* B, const float* bias,
                     auto* Cb, const H* A0b, const H* A1b, const H* Bb,
                     int M, int Nfull, int K, int seg_shift, float sc) {
        using T = typename std::remove_pointer<decltype(C)>::type;
        dim3 g(Nfull / 64, M / 128, 2);
        mma_nt_kernel<T><<<g, 128, SMEM_GEMM>>>(C, A0, A1p, A2p, B, bias,
                                                Cb, A0b, A1b, Bb,
                                                Nfull, K, seg_shift, sc);
    };

    // (1) fused operand conversion
    convert_all_kernel<<<(CVT_TOTAL + 255) / 256, 256>>>(
        sp, om1, om2, q_w, k1_w, k2_w, v_w, c1_w,
        sph, om1h, om2h, qwh, k1wh, k2wh, vwh, c1wh);

    // (2-5) projections
    gemm1(qh,  sph,  (const H*)nullptr, (const H*)nullptr, qwh,  q_b,  NROWS, CH, 512, 9, 1.0f);
    gemm1(k1h, om1h, (const H*)nullptr, (const H*)nullptr, k1wh, k1_b, NROWS, CH, 512, 9, 1.0f);
    gemm1(k2h, om2h, (const H*)nullptr, (const H*)nullptr, k2wh, k2_b, NROWS, CH, 512, 9, 1.0f);
    gemm1(vh,  sph,  om1h, om2h, vwh, v_b, NROWS, CH, 1536, 9, 1.0f);

    // (6) S1 = q k1^T and S2 = q k2^T in one batched launch (fp16 out)
    gemm2(S1, qh, (const H*)nullptr, (const H*)nullptr, k1h, nullptr,
          S2, (const H*)nullptr, (const H*)nullptr, k2h,
          NROWS, NROWS, 512, 9, scale);

    // (7) batched softmax (both attentions)
    softmax_kernel<<<dim3(NROWS, 2), 256>>>(S1, S2, P1, P2);

    // (8) V transpose
    transpose_h_kernel<<<dim3(CH / 32, NROWS / 32), 256>>>(vTh, vh);

    // (9) attn1 = P1 vT^T, attn2 = P2 vT^T (batched)
    gemm2(attn1, P1, (const H*)nullptr, (const H*)nullptr, vTh, nullptr,
          attn2, P2, (const H*)nullptr, (const H*)nullptr,
          NROWS, CH, NROWS, 13, 1.0f);

    // (10) gate logits a1,a2 (batched)
    gemm2(a1, sph, om1h, (const H*)nullptr, c1wh, c1_b,
          a2, (const H*)nullptr, om2h, (const H*)nullptr,
          NROWS, CH, 1024, 9, 1.0f);

    // (11) fused gate + combine
    combine_kernel<<<elemBlocks, 256>>>(out, a1, a2, attn1, attn2, (int)NC);
}

// round 9
// speedup vs baseline: 1.3205x; 1.3205x over previous
#include <cuda_runtime.h>
#include <cuda_fp16.h>
#include <cstdint>

#define NROWS 8192
#define CH    512
#define NC    ((size_t)NROWS * CH)          // 4,194,304
#define S_ELEMS ((size_t)NROWS * NROWS)     // 67,108,864

// float region: a1,a2,attn1,attn2 (4*NC)
// half  region: sph,om1h,om2h,qh,k1h,k2h,vh,vTh (8*NC), S1,S2,P1,P2 (4*S_ELEMS), weights
#define FLOAT_REGION (4 * NC)
#define HALF_REGION  (8 * NC + 4 * S_ELEMS + 2097152)
__device__ float g_scratch[FLOAT_REGION + HALF_REGION / 2 + 1024];

// ===========================================================================
// helpers
// ===========================================================================
__device__ __forceinline__ uint32_t smem_u32(const void* p) {
    uint32_t a;
    asm("{ .reg .u64 t; cvta.to.shared.u64 t, %1; cvt.u32.u64 %0, t; }"
        : "=r"(a) : "l"(p));
    return a;
}
__device__ __forceinline__ void cp16(uint32_t dst, const void* src) {
    asm volatile("cp.async.cg.shared.global [%0], [%1], 16;" :: "r"(dst), "l"(src));
}
__device__ __forceinline__ void ldmx4(uint32_t* r, uint32_t addr) {
    asm volatile("ldmatrix.sync.aligned.m8n8.x4.shared.b16 {%0,%1,%2,%3}, [%4];"
                 : "=r"(r[0]), "=r"(r[1]), "=r"(r[2]), "=r"(r[3]) : "r"(addr));
}
__device__ __forceinline__ void mma_f16(float* d, const uint32_t* a,
                                        uint32_t b0, uint32_t b1) {
    asm volatile(
        "mma.sync.aligned.m16n8k16.row.col.f32.f16.f16.f32 "
        "{%0,%1,%2,%3}, {%4,%5,%6,%7}, {%8,%9}, {%0,%1,%2,%3};"
        : "+f"(d[0]), "+f"(d[1]), "+f"(d[2]), "+f"(d[3])
        : "r"(a[0]), "r"(a[1]), "r"(a[2]), "r"(a[3]), "r"(b0), "r"(b1));
}
// 128B-row XOR-8 swizzle: 16B chunk c (0..7) of row r -> conflict-free
// for both cp.async fills and every ldmatrix 8-row phase.
__device__ __forceinline__ uint32_t sw128(int r, int c) {
    return (uint32_t)(((c ^ (r & 7)) * 16));
}

// ===========================================================================
// fp16 NT GEMM, tile 128x128, BK=64, 3-stage cp.async, 256 threads
// (8 warps as 4m x 2n, per-warp 32x64), 2 CTAs/SM.
// grid.z batching via alternate pointers (blockIdx.z==1 swaps non-null alts).
//   A: fp16 K-major, optionally 3-seg K-concat (seg len = 1<<seg_shift)
//   B: fp16 [Nfull, K] row-major
// ===========================================================================
#define STAGES   3
#define A_TILE_B 16384                 // 128 rows * 128B
#define STAGE_B  32768
#define SMEM_GEMM (STAGES * STAGE_B)   // 98304

template <typename OutT>
__global__ void __launch_bounds__(256, 2)
mma_nt_kernel(OutT* C, const __half* A0, const __half* A1, const __half* A2,
              const __half* B, const float* bias,
              OutT* Cb, const __half* A0b, const __half* A1b, const __half* Bb,
              int Nfull, int K, int seg_shift, float scale)
{
    if (blockIdx.z == 1) {
        if (Cb)  C  = Cb;
        if (A0b) A0 = A0b;
        if (A1b) A1 = A1b;
        if (Bb)  B  = Bb;
    }
    extern __shared__ char sm[];
    const uint32_t sbase = smem_u32(sm);
    const int tid  = threadIdx.x;
    const int warp = tid >> 5;
    const int lane = tid & 31;
    const int wm   = warp >> 1;          // 0..3
    const int wn   = warp & 1;           // 0..1
    const int m0   = blockIdx.y * 128;
    const int n0   = blockIdx.x * 128;
    const int nch  = K >> 6;             // 64-wide K chunks
    const int segmask = (1 << seg_shift) - 1;

    const int lr  = tid >> 1;            // loader row 0..127
    const int lc0 = (tid & 1) * 4;       // first of 4 chunks

    auto issue = [&](int c) {
        const int kb  = c << 6;
        const int seg = kb >> seg_shift;
        const __half* Asrc = (seg == 0) ? A0 : ((seg == 1) ? A1 : A2);
        const __half* ap = Asrc + (((size_t)(m0 + lr)) << seg_shift) + (kb & segmask);
        const __half* bp = B + (size_t)(n0 + lr) * K + kb;
        const uint32_t st  = sbase + (c % STAGES) * STAGE_B;
        const uint32_t sta = st + lr * 128;
        const uint32_t stb = st + A_TILE_B + lr * 128;
#pragma unroll
        for (int j = 0; j < 4; j++) {
            const int ch = lc0 + j;
            cp16(sta + sw128(lr, ch), ap + ch * 8);
            cp16(stb + sw128(lr, ch), bp + ch * 8);
        }
        asm volatile("cp.async.commit_group;" ::: "memory");
    };

    float acc[2][8][4];
#pragma unroll
    for (int mt = 0; mt < 2; mt++)
#pragma unroll
        for (int nt = 0; nt < 8; nt++)
#pragma unroll
            for (int r = 0; r < 4; r++) acc[mt][nt][r] = 0.0f;

    issue(0); issue(1);

    const int l15 = lane & 15;
    const int lhi = lane >> 4;
    // offsets for ks in {0,1}; ks+2 = same offset ^ 64 (chunk bit-2 flip,
    // valid because chunk index 2*ks+lhi <= 3 has bit 2 clear)
    uint32_t aoff[2][2], boff[4][2];
#pragma unroll
    for (int mt = 0; mt < 2; mt++)
#pragma unroll
        for (int ks = 0; ks < 2; ks++) {
            const int r = wm * 32 + mt * 16 + l15;
            aoff[mt][ks] = (uint32_t)r * 128 + sw128(r, 2 * ks + lhi);
        }
#pragma unroll
    for (int np = 0; np < 4; np++)
#pragma unroll
        for (int ks = 0; ks < 2; ks++) {
            const int r = wn * 64 + np * 16 + l15;
            boff[np][ks] = A_TILE_B + (uint32_t)r * 128 + sw128(r, 2 * ks + lhi);
        }

    for (int c = 0; c < nch; c++) {
        asm volatile("cp.async.wait_group %0;" :: "n"(1) : "memory");
        __syncthreads();
        if (c + 2 < nch) issue(c + 2);
        else asm volatile("cp.async.commit_group;" ::: "memory");

        const uint32_t st = sbase + (c % STAGES) * STAGE_B;

        uint32_t afc[2][4], afn[2][4], bf[4][4];
        ldmx4(afc[0], st + aoff[0][0]);
        ldmx4(afc[1], st + aoff[1][0]);
#pragma unroll
        for (int ks = 0; ks < 4; ks++) {
            if (ks < 3) {                       // prefetch next ks A frags
                const int kn = ks + 1;
                const uint32_t xn = (kn & 2) ? 64u : 0u;
                ldmx4(afn[0], st + (aoff[0][kn & 1] ^ xn));
                ldmx4(afn[1], st + (aoff[1][kn & 1] ^ xn));
            }
            const uint32_t x = (ks & 2) ? 64u : 0u;
#pragma unroll
            for (int np = 0; np < 4; np++)
                ldmx4(bf[np], st + (boff[np][ks & 1] ^ x));
#pragma unroll
            for (int mt = 0; mt < 2; mt++)
#pragma unroll
                for (int np = 0; np < 4; np++) {
                    mma_f16(acc[mt][2 * np],     afc[mt], bf[np][0], bf[np][2]);
                    mma_f16(acc[mt][2 * np + 1], afc[mt], bf[np][1], bf[np][3]);
                }
#pragma unroll
            for (int mt = 0; mt < 2; mt++)
#pragma unroll
                for (int q = 0; q < 4; q++) afc[mt][q] = afn[mt][q];
        }
    }

    const int frow = lane >> 2;
    const int fcol = lane & 3;
#pragma unroll
    for (int mt = 0; mt < 2; mt++) {
        const int row = m0 + wm * 32 + mt * 16 + frow;
#pragma unroll
        for (int nt = 0; nt < 8; nt++) {
            const int col = n0 + wn * 64 + nt * 8 + fcol * 2;
            float b0 = 0.0f, b1 = 0.0f;
            if (bias != nullptr) { b0 = bias[col]; b1 = bias[col + 1]; }
            float x0 = acc[mt][nt][0] * scale + b0;
            float x1 = acc[mt][nt][1] * scale + b1;
            float x2 = acc[mt][nt][2] * scale + b0;
            float x3 = acc[mt][nt][3] * scale + b1;
            if constexpr (sizeof(OutT) == 2) {
                *(__half2*)((__half*)C + (size_t)row * Nfull + col) =
                    __floats2half2_rn(x0, x1);
                *(__half2*)((__half*)C + (size_t)(row + 8) * Nfull + col) =
                    __floats2half2_rn(x2, x3);
            } else {
                *(float2*)((float*)C + (size_t)row * Nfull + col) = make_float2(x0, x1);
                *(float2*)((float*)C + (size_t)(row + 8) * Nfull + col) = make_float2(x2, x3);
            }
        }
    }
}

// ===========================================================================
// Fused fp32->fp16 conversion for all 8 operands
// ===========================================================================
#define SEG_IN  ((int)(NC / 4))
#define SEG_W5  65536
#define SEG_VW  196608
#define SEG_CW  131072
#define CVT_TOTAL (3 * SEG_IN + 3 * SEG_W5 + SEG_VW + SEG_CW)

__global__ void __launch_bounds__(256)
convert_all_kernel(const float* __restrict__ sp, const float* __restrict__ om1,
                   const float* __restrict__ om2, const float* __restrict__ qw,
                   const float* __restrict__ k1w, const float* __restrict__ k2w,
                   const float* __restrict__ vw, const float* __restrict__ cw,
                   __half* __restrict__ sph, __half* __restrict__ om1h,
                   __half* __restrict__ om2h, __half* __restrict__ qwh,
                   __half* __restrict__ k1wh, __half* __restrict__ k2wh,
                   __half* __restrict__ vwh, __half* __restrict__ cwh)
{
    int i = blockIdx.x * 256 + threadIdx.x;
    if (i >= CVT_TOTAL) return;
    const float* src; __half* dst; int off = i;
    if (off < SEG_IN) { src = sp; dst = sph; }
    else if ((off -= SEG_IN) < SEG_IN) { src = om1; dst = om1h; }
    else if ((off -= SEG_IN) < SEG_IN) { src = om2; dst = om2h; }
    else if ((off -= SEG_IN) < SEG_W5) { src = qw; dst = qwh; }
    else if ((off -= SEG_W5) < SEG_W5) { src = k1w; dst = k1wh; }
    else if ((off -= SEG_W5) < SEG_W5) { src = k2w; dst = k2wh; }
    else if ((off -= SEG_W5) < SEG_VW) { src = vw; dst = vwh; }
    else { off -= SEG_VW; src = cw; dst = cwh; }
    float4 x = ((const float4*)src)[off];
    ((__half2*)dst)[2 * off]     = __floats2half2_rn(x.x, x.y);
    ((__half2*)dst)[2 * off + 1] = __floats2half2_rn(x.z, x.w);
}

__global__ void __launch_bounds__(256)
transpose_h_kernel(__half* __restrict__ out, const __half* __restrict__ in)
{
    __shared__ __half tile[32][34];
    const int tx = threadIdx.x & 31;
    const int ty = threadIdx.x >> 5;
    const int x0 = blockIdx.x * 32;
    const int y0 = blockIdx.y * 32;
#pragma unroll
    for (int j = 0; j < 32; j += 8)
        tile[ty + j][tx] = in[(size_t)(y0 + ty + j) * CH + x0 + tx];
    __syncthreads();
#pragma unroll
    for (int j = 0; j < 32; j += 8)
        out[(size_t)(x0 + ty + j) * NROWS + y0 + tx] = tile[tx][ty + j];
}

// ===========================================================================
// Row softmax over 8192 cols, fp16 in / fp16 out, batched over 2 matrices
// via blockIdx.y. Math in fp32.
// ===========================================================================
__global__ void __launch_bounds__(256)
softmax_kernel(const __half* __restrict__ S1, const __half* __restrict__ S2,
               __half* __restrict__ P1, __half* __restrict__ P2)
{
    const int tid = threadIdx.x;
    const size_t roff = (size_t)blockIdx.x * NROWS;
    const uint4* pr = (const uint4*)((blockIdx.y ? S2 : S1) + roff);
    uint4* po = (uint4*)((blockIdx.y ? P2 : P1) + roff);
    __shared__ float red1[8];
    __shared__ float red2[8];

    float v[32];
#pragma unroll
    for (int i = 0; i < 4; i++) {
        uint4 u = pr[i * 256 + tid];
        float2 f;
        f = __half22float2(*(__half2*)&u.x); v[i*8+0] = f.x; v[i*8+1] = f.y;
        f = __half22float2(*((__half2*)&u.x + 1)); v[i*8+2] = f.x; v[i*8+3] = f.y;
        f = __half22float2(*(__half2*)&u.z); v[i*8+4] = f.x; v[i*8+5] = f.y;
        f = __half22float2(*((__half2*)&u.z + 1)); v[i*8+6] = f.x; v[i*8+7] = f.y;
    }

    float m = -3.0e38f;
#pragma unroll
    for (int j = 0; j < 32; j++) m = fmaxf(m, v[j]);
#pragma unroll
    for (int o = 16; o > 0; o >>= 1)
        m = fmaxf(m, __shfl_xor_sync(0xffffffff, m, o));
    if ((tid & 31) == 0) red1[tid >> 5] = m;
    __syncthreads();
    m = red1[0];
#pragma unroll
    for (int i = 1; i < 8; i++) m = fmaxf(m, red1[i]);

    float s = 0.0f;
#pragma unroll
    for (int j = 0; j < 32; j++) { v[j] = __expf(v[j] - m); s += v[j]; }
#pragma unroll
    for (int o = 16; o > 0; o >>= 1)
        s += __shfl_xor_sync(0xffffffff, s, o);
    if ((tid & 31) == 0) red2[tid >> 5] = s;
    __syncthreads();
    s = 0.0f;
#pragma unroll
    for (int i = 0; i < 8; i++) s += red2[i];
    const float inv = 1.0f / s;

#pragma unroll
    for (int i = 0; i < 4; i++) {
        uint4 u;
        *(__half2*)&u.x       = __floats2half2_rn(v[i*8+0] * inv, v[i*8+1] * inv);
        *((__half2*)&u.x + 1) = __floats2half2_rn(v[i*8+2] * inv, v[i*8+3] * inv);
        *(__half2*)&u.z       = __floats2half2_rn(v[i*8+4] * inv, v[i*8+5] * inv);
        *((__half2*)&u.z + 1) = __floats2half2_rn(v[i*8+6] * inv, v[i*8+7] * inv);
        po[i * 256 + tid] = u;
    }
}

// fused gate + combine: g = sigmoid(sigmoid(a1)-sigmoid(a2));
// out = g*attn1 + (1-g)*attn2
__global__ void __launch_bounds__(256)
combine_kernel(float* __restrict__ out, const float* __restrict__ a1,
               const float* __restrict__ a2, const float* __restrict__ A1,
               const float* __restrict__ A2, int n)
{
    int i = blockIdx.x * 256 + threadIdx.x;
    if (i < n) {
        float s1 = 1.0f / (1.0f + __expf(-a1[i]));
        float s2 = 1.0f / (1.0f + __expf(-a2[i]));
        float g  = 1.0f / (1.0f + __expf(-(s1 - s2)));
        out[i] = g * A1[i] + (1.0f - g) * A2[i];
    }
}

// ===========================================================================
extern "C" void kernel_launch(void* const* d_in, const int* in_sizes, int n_in,
                              void* d_out, int out_size)
{
    const float* sp   = (const float*)d_in[0];
    const float* om1  = (const float*)d_in[1];
    const float* om2  = (const float*)d_in[2];
    const float* q_w  = (const float*)d_in[3];
    const float* q_b  = (const float*)d_in[4];
    const float* k1_w = (const float*)d_in[5];
    const float* k1_b = (const float*)d_in[6];
    const float* k2_w = (const float*)d_in[7];
    const float* k2_b = (const float*)d_in[8];
    const float* v_w  = (const float*)d_in[9];
    const float* v_b  = (const float*)d_in[10];
    const float* c1_w = (const float*)d_in[11];
    const float* c1_b = (const float*)d_in[12];
    float* out = (float*)d_out;

    float* base = nullptr;
    cudaGetSymbolAddress((void**)&base, g_scratch);
    float* a1    = base + 0 * NC;
    float* a2    = base + 1 * NC;
    float* attn1 = base + 2 * NC;
    float* attn2 = base + 3 * NC;
    __half* hb   = (__half*)(base + FLOAT_REGION);
    __half* sph  = hb + 0 * NC;
    __half* om1h = hb + 1 * NC;
    __half* om2h = hb + 2 * NC;
    __half* qh   = hb + 3 * NC;
    __half* k1h  = hb + 4 * NC;
    __half* k2h  = hb + 5 * NC;
    __half* vh   = hb + 6 * NC;
    __half* vTh  = hb + 7 * NC;
    __half* S1   = hb + 8 * NC;
    __half* S2   = S1 + S_ELEMS;
    __half* P1   = S2 + S_ELEMS;
    __half* P2   = P1 + S_ELEMS;
    __half* wts  = P2 + S_ELEMS;
    __half* qwh  = wts;
    __half* k1wh = wts + 262144;
    __half* k2wh = wts + 524288;
    __half* vwh  = wts + 786432;
    __half* c1wh = wts + 1572864;

    cudaFuncSetAttribute(mma_nt_kernel<float>,
                         cudaFuncAttributeMaxDynamicSharedMemorySize, SMEM_GEMM);
    cudaFuncSetAttribute(mma_nt_kernel<__half>,
                         cudaFuncAttributeMaxDynamicSharedMemorySize, SMEM_GEMM);

    const float scale = 0.044194173824159223f;  // 1/sqrt(512)
    const int elemBlocks = (int)((NC + 255) / 256);
    typedef __half H;

    auto gemm1 = [&](auto* C, const H* A0, const H* A1p, const H* A2p,
                     const H* B, const float* bias, int M, int Nfull, int K,
                     int seg_shift, float sc) {
        using T = typename std::remove_pointer<decltype(C)>::type;
        dim3 g(Nfull / 128, M / 128, 1);
        mma_nt_kernel<T><<<g, 256, SMEM_GEMM>>>(C, A0, A1p, A2p, B, bias,
                                                (T*)nullptr, nullptr, nullptr, nullptr,
                                                Nfull, K, seg_shift, sc);
    };
    auto gemm2 = [&](auto* C, const H* A0, const H* A1p, const H* A2p,
                     const H* B, const float* bias,
                     auto* Cb, const H* A0b, const H* A1b, const H* Bb,
                     int M, int Nfull, int K, int seg_shift, float sc) {
        using T = typename std::remove_pointer<decltype(C)>::type;
        dim3 g(Nfull / 128, M / 128, 2);
        mma_nt_kernel<T><<<g, 256, SMEM_GEMM>>>(C, A0, A1p, A2p, B, bias,
                                                Cb, A0b, A1b, Bb,
                                                Nfull, K, seg_shift, sc);
    };

    // (1) fused operand conversion
    convert_all_kernel<<<(CVT_TOTAL + 255) / 256, 256>>>(
        sp, om1, om2, q_w, k1_w, k2_w, v_w, c1_w,
        sph, om1h, om2h, qwh, k1wh, k2wh, vwh, c1wh);

    // (2-5) projections
    gemm1(qh,  sph,  (const H*)nullptr, (const H*)nullptr, qwh,  q_b,  NROWS, CH, 512, 9, 1.0f);
    gemm1(k1h, om1h, (const H*)nullptr, (const H*)nullptr, k1wh, k1_b, NROWS, CH, 512, 9, 1.0f);
    gemm1(k2h, om2h, (const H*)nullptr, (const H*)nullptr, k2wh, k2_b, NROWS, CH, 512, 9, 1.0f);
    gemm1(vh,  sph,  om1h, om2h, vwh, v_b, NROWS, CH, 1536, 9, 1.0f);

    // (6) S1 = q k1^T and S2 = q k2^T in one batched launch (fp16 out)
    gemm2(S1, qh, (const H*)nullptr, (const H*)nullptr, k1h, nullptr,
          S2, (const H*)nullptr, (const H*)nullptr, k2h,
          NROWS, NROWS, 512, 9, scale);

    // (7) batched softmax (both attentions)
    softmax_kernel<<<dim3(NROWS, 2), 256>>>(S1, S2, P1, P2);

    // (8) V transpose
    transpose_h_kernel<<<dim3(CH / 32, NROWS / 32), 256>>>(vTh, vh);

    // (9) attn1 = P1 vT^T, attn2 = P2 vT^T (batched)
    gemm2(attn1, P1, (const H*)nullptr, (const H*)nullptr, vTh, nullptr,
          attn2, P2, (const H*)nullptr, (const H*)nullptr,
          NROWS, CH, NROWS, 13, 1.0f);

    // (10) gate logits a1,a2 (batched)
    gemm2(a1, sph, om1h, (const H*)nullptr, c1wh, c1_b,
          a2, (const H*)nullptr, om2h, (const H*)nullptr,
          NROWS, CH, 1024, 9, 1.0f);

    // (11) fused gate + combine
    combine_kernel<<<elemBlocks, 256>>>(out, a1, a2, attn1, attn2, (int)NC);
}

// round 10
// speedup vs baseline: 1.3517x; 1.0236x over previous
#include <cuda_runtime.h>
#include <cuda_fp16.h>
#include <cstdint>

#define NROWS 8192
#define CH    512
#define NC    ((size_t)NROWS * CH)          // 4,194,304
#define S_ELEMS ((size_t)NROWS * NROWS)     // 67,108,864

// float region: u,w1,w2,attn1,attn2 (5*NC)
// half  region: sph,om1h,om2h,qh,k1h,k2h,vh,vTh (8*NC), S1,S2,P1,P2 (4*S_ELEMS), weights
#define FLOAT_REGION (5 * NC)
#define HALF_REGION  (8 * NC + 4 * S_ELEMS + 2097152)
__device__ float g_scratch[FLOAT_REGION + HALF_REGION / 2 + 1024];

// ===========================================================================
// helpers
// ===========================================================================
__device__ __forceinline__ uint32_t smem_u32(const void* p) {
    uint32_t a;
    asm("{ .reg .u64 t; cvta.to.shared.u64 t, %1; cvt.u32.u64 %0, t; }"
        : "=r"(a) : "l"(p));
    return a;
}
__device__ __forceinline__ void cp16(uint32_t dst, const void* src) {
    asm volatile("cp.async.cg.shared.global [%0], [%1], 16;" :: "r"(dst), "l"(src));
}
__device__ __forceinline__ void ldmx4(uint32_t* r, uint32_t addr) {
    asm volatile("ldmatrix.sync.aligned.m8n8.x4.shared.b16 {%0,%1,%2,%3}, [%4];"
                 : "=r"(r[0]), "=r"(r[1]), "=r"(r[2]), "=r"(r[3]) : "r"(addr));
}
__device__ __forceinline__ void mma_f16(float* d, const uint32_t* a,
                                        uint32_t b0, uint32_t b1) {
    asm volatile(
        "mma.sync.aligned.m16n8k16.row.col.f32.f16.f16.f32 "
        "{%0,%1,%2,%3}, {%4,%5,%6,%7}, {%8,%9}, {%0,%1,%2,%3};"
        : "+f"(d[0]), "+f"(d[1]), "+f"(d[2]), "+f"(d[3])
        : "r"(a[0]), "r"(a[1]), "r"(a[2]), "r"(a[3]), "r"(b0), "r"(b1));
}
// 16B-chunk swizzle within a 64B row -> conflict-free ldmatrix + cp.async
__device__ __forceinline__ uint32_t sw16(int r, int c) {
    return (uint32_t)((c ^ ((r >> 1) & 3)) * 16);
}

// Up to 3 problem instances selected by blockIdx.z
struct GemmBatch {
    void*         C[3];
    const __half* A0[3];
    const __half* A1[3];     // K-concat segment 2 (nullptr if none)
    const __half* A2[3];     // K-concat segment 3
    const __half* B[3];
    const float*  bias[3];
};

// ===========================================================================
// fp16 NT GEMM, tile 128x128, BK=32, 4-stage cp.async, 256 threads
// (8 warps 4m x 2n, per-warp 32x64), 2 CTAs/SM.  (R7 engine, unchanged.)
//   A: fp16 K-major, optionally 3-seg K-concat (seg len = 1<<seg_shift)
//   B: fp16 [Nfull, K] rows with leading dim ldb
// fp16 output goes through a smem-staged fully-coalesced store.
// ===========================================================================
#define STAGES   4
#define A_TILE_B 8192                  // 128 rows * 64B
#define STAGE_B  16384
#define SMEM_GEMM (STAGES * STAGE_B)   // 65536

template <typename OutT>
__global__ void __launch_bounds__(256, 2)
mma_nt_kernel(GemmBatch bt, int Nfull, int K, int ldb, int seg_shift, float scale)
{
    const int z = blockIdx.z;
    OutT* C           = (OutT*)bt.C[z];
    const __half* A0  = bt.A0[z];
    const __half* A1  = bt.A1[z];
    const __half* A2  = bt.A2[z];
    const __half* B   = bt.B[z];
    const float* bias = bt.bias[z];

    extern __shared__ char sm[];
    const uint32_t sbase = smem_u32(sm);
    const int tid  = threadIdx.x;
    const int warp = tid >> 5;
    const int lane = tid & 31;
    const int wm   = warp >> 1;          // 0..3
    const int wn   = warp & 1;           // 0..1
    const int m0   = blockIdx.y * 128;
    const int n0   = blockIdx.x * 128;
    const int nch  = K >> 5;
    const int segmask = (1 << seg_shift) - 1;

    const int lr = tid >> 1;
    const int lc0 = (tid & 1) * 2;

    auto issue = [&](int c) {
        const int kb  = c << 5;
        const int seg = kb >> seg_shift;
        const __half* Asrc = (seg == 0) ? A0 : ((seg == 1) ? A1 : A2);
        const __half* ap = Asrc + (((size_t)(m0 + lr)) << seg_shift) + (kb & segmask);
        const __half* bp = B + (size_t)(n0 + lr) * ldb + kb;
        const uint32_t st = sbase + (c % STAGES) * STAGE_B + lr * 64;
#pragma unroll
        for (int j = 0; j < 2; j++) {
            const int ch = lc0 + j;
            cp16(st + sw16(lr, ch), ap + ch * 8);
            cp16(st + A_TILE_B + sw16(lr, ch), bp + ch * 8);
        }
        asm volatile("cp.async.commit_group;" ::: "memory");
    };

    float acc[2][8][4];
#pragma unroll
    for (int mt = 0; mt < 2; mt++)
#pragma unroll
        for (int nt = 0; nt < 8; nt++)
#pragma unroll
            for (int r = 0; r < 4; r++) acc[mt][nt][r] = 0.0f;

    issue(0); issue(1); issue(2);

    const int l15 = lane & 15;
    const int lhi = lane >> 4;
    uint32_t aoff[2][2], boff[4][2];
#pragma unroll
    for (int mt = 0; mt < 2; mt++)
#pragma unroll
        for (int ks = 0; ks < 2; ks++) {
            const int r = wm * 32 + mt * 16 + l15;
            aoff[mt][ks] = (uint32_t)r * 64 + sw16(r, 2 * ks + lhi);
        }
#pragma unroll
    for (int np = 0; np < 4; np++)
#pragma unroll
        for (int ks = 0; ks < 2; ks++) {
            const int r = wn * 64 + np * 16 + l15;
            boff[np][ks] = A_TILE_B + (uint32_t)r * 64 + sw16(r, 2 * ks + lhi);
        }

    for (int c = 0; c < nch; c++) {
        asm volatile("cp.async.wait_group %0;" :: "n"(2) : "memory");
        __syncthreads();
        if (c + 3 < nch) issue(c + 3);
        else asm volatile("cp.async.commit_group;" ::: "memory");

        const uint32_t st = sbase + (c % STAGES) * STAGE_B;

        uint32_t af0[2][4], af1[2][4], bf[4][4];
        ldmx4(af0[0], st + aoff[0][0]);
        ldmx4(af0[1], st + aoff[1][0]);
        ldmx4(af1[0], st + aoff[0][1]);
        ldmx4(af1[1], st + aoff[1][1]);
#pragma unroll
        for (int np = 0; np < 4; np++) ldmx4(bf[np], st + boff[np][0]);
#pragma unroll
        for (int mt = 0; mt < 2; mt++)
#pragma unroll
            for (int np = 0; np < 4; np++) {
                mma_f16(acc[mt][2 * np],     af0[mt], bf[np][0], bf[np][2]);
                mma_f16(acc[mt][2 * np + 1], af0[mt], bf[np][1], bf[np][3]);
            }
#pragma unroll
        for (int np = 0; np < 4; np++) ldmx4(bf[np], st + boff[np][1]);
#pragma unroll
        for (int mt = 0; mt < 2; mt++)
#pragma unroll
            for (int np = 0; np < 4; np++) {
                mma_f16(acc[mt][2 * np],     af1[mt], bf[np][0], bf[np][2]);
                mma_f16(acc[mt][2 * np + 1], af1[mt], bf[np][1], bf[np][3]);
            }
    }

    // ------------------------------ epilogue -------------------------------
    const int frow = lane >> 2;
    const int fcol = lane & 3;
    if constexpr (sizeof(OutT) == 2) {
        // stage half tile in smem (stride 136 halves = 272B, 16B-aligned rows)
        __syncthreads();                    // done reading pipeline stages
        __half* sbuf = (__half*)sm;
#pragma unroll
        for (int mt = 0; mt < 2; mt++) {
            const int row = wm * 32 + mt * 16 + frow;
#pragma unroll
            for (int nt = 0; nt < 8; nt++) {
                const int col = n0 + wn * 64 + nt * 8 + fcol * 2;
                float b0 = 0.0f, b1 = 0.0f;
                if (bias != nullptr) { b0 = bias[col]; b1 = bias[col + 1]; }
                const int lcol = wn * 64 + nt * 8 + fcol * 2;
                *(__half2*)(sbuf + (size_t)row * 136 + lcol) =
                    __floats2half2_rn(acc[mt][nt][0] * scale + b0,
                                      acc[mt][nt][1] * scale + b1);
                *(__half2*)(sbuf + (size_t)(row + 8) * 136 + lcol) =
                    __floats2half2_rn(acc[mt][nt][2] * scale + b0,
                                      acc[mt][nt][3] * scale + b1);
            }
        }
        __syncthreads();
        // coalesced streamout: thread t -> row t/2, 64-half run
        const int orow  = tid >> 1;
        const int obase = (tid & 1) * 64;
        const uint4* srow = (const uint4*)(sbuf + (size_t)orow * 136 + obase);
        uint4* crow = (uint4*)((__half*)C + (size_t)(m0 + orow) * Nfull + n0 + obase);
#pragma unroll
        for (int j = 0; j < 8; j++) crow[j] = srow[j];
    } else {
#pragma unroll
        for (int mt = 0; mt < 2; mt++) {
            const int row = m0 + wm * 32 + mt * 16 + frow;
#pragma unroll
            for (int nt = 0; nt < 8; nt++) {
                const int col = n0 + wn * 64 + nt * 8 + fcol * 2;
                float b0 = 0.0f, b1 = 0.0f;
                if (bias != nullptr) { b0 = bias[col]; b1 = bias[col + 1]; }
                *(float2*)((float*)C + (size_t)row * Nfull + col) =
                    make_float2(acc[mt][nt][0] * scale + b0,
                                acc[mt][nt][1] * scale + b1);
                *(float2*)((float*)C + (size_t)(row + 8) * Nfull + col) =
                    make_float2(acc[mt][nt][2] * scale + b0,
                                acc[mt][nt][3] * scale + b1);
            }
        }
    }
}

// ===========================================================================
// Fused fp32->fp16 conversion for all 8 operands
// ===========================================================================
#define SEG_IN  ((int)(NC / 4))
#define SEG_W5  65536
#define SEG_VW  196608
#define SEG_CW  131072
#define CVT_TOTAL (3 * SEG_IN + 3 * SEG_W5 + SEG_VW + SEG_CW)

__global__ void __launch_bounds__(256)
convert_all_kernel(const float* __restrict__ sp, const float* __restrict__ om1,
                   const float* __restrict__ om2, const float* __restrict__ qw,
                   const float* __restrict__ k1w, const float* __restrict__ k2w,
                   const float* __restrict__ vw, const float* __restrict__ cw,
                   __half* __restrict__ sph, __half* __restrict__ om1h,
                   __half* __restrict__ om2h, __half* __restrict__ qwh,
                   __half* __restrict__ k1wh, __half* __restrict__ k2wh,
                   __half* __restrict__ vwh, __half* __restrict__ cwh)
{
    int i = blockIdx.x * 256 + threadIdx.x;
    if (i >= CVT_TOTAL) return;
    const float* src; __half* dst; int off = i;
    if (off < SEG_IN) { src = sp; dst = sph; }
    else if ((off -= SEG_IN) < SEG_IN) { src = om1; dst = om1h; }
    else if ((off -= SEG_IN) < SEG_IN) { src = om2; dst = om2h; }
    else if ((off -= SEG_IN) < SEG_W5) { src = qw; dst = qwh; }
    else if ((off -= SEG_W5) < SEG_W5) { src = k1w; dst = k1wh; }
    else if ((off -= SEG_W5) < SEG_W5) { src = k2w; dst = k2wh; }
    else if ((off -= SEG_W5) < SEG_VW) { src = vw; dst = vwh; }
    else { off -= SEG_VW; src = cw; dst = cwh; }
    float4 x = ((const float4*)src)[off];
    ((__half2*)dst)[2 * off]     = __floats2half2_rn(x.x, x.y);
    ((__half2*)dst)[2 * off + 1] = __floats2half2_rn(x.z, x.w);
}

__global__ void __launch_bounds__(256)
transpose_h_kernel(__half* __restrict__ out, const __half* __restrict__ in)
{
    __shared__ __half tile[32][34];
    const int tx = threadIdx.x & 31;
    const int ty = threadIdx.x >> 5;
    const int x0 = blockIdx.x * 32;
    const int y0 = blockIdx.y * 32;
#pragma unroll
    for (int j = 0; j < 32; j += 8)
        tile[ty + j][tx] = in[(size_t)(y0 + ty + j) * CH + x0 + tx];
    __syncthreads();
#pragma unroll
    for (int j = 0; j < 32; j += 8)
        out[(size_t)(x0 + ty + j) * NROWS + y0 + tx] = tile[tx][ty + j];
}

// ===========================================================================
// Row softmax over 8192 cols, fp16 in / fp16 out, batched over 2 matrices
// via blockIdx.y. Math in fp32.
// ===========================================================================
__global__ void __launch_bounds__(256)
softmax_kernel(const __half* __restrict__ S1, const __half* __restrict__ S2,
               __half* __restrict__ P1, __half* __restrict__ P2)
{
    const int tid = threadIdx.x;
    const size_t roff = (size_t)blockIdx.x * NROWS;
    const uint4* pr = (const uint4*)((blockIdx.y ? S2 : S1) + roff);
    uint4* po = (uint4*)((blockIdx.y ? P2 : P1) + roff);
    __shared__ float red1[8];
    __shared__ float red2[8];

    float v[32];
#pragma unroll
    for (int i = 0; i < 4; i++) {
        uint4 u = pr[i * 256 + tid];
        float2 f;
        f = __half22float2(*(__half2*)&u.x); v[i*8+0] = f.x; v[i*8+1] = f.y;
        f = __half22float2(*((__half2*)&u.x + 1)); v[i*8+2] = f.x; v[i*8+3] = f.y;
        f = __half22float2(*(__half2*)&u.z); v[i*8+4] = f.x; v[i*8+5] = f.y;
        f = __half22float2(*((__half2*)&u.z + 1)); v[i*8+6] = f.x; v[i*8+7] = f.y;
    }

    float m = -3.0e38f;
#pragma unroll
    for (int j = 0; j < 32; j++) m = fmaxf(m, v[j]);
#pragma unroll
    for (int o = 16; o > 0; o >>= 1)
        m = fmaxf(m, __shfl_xor_sync(0xffffffff, m, o));
    if ((tid & 31) == 0) red1[tid >> 5] = m;
    __syncthreads();
    m = red1[0];
#pragma unroll
    for (int i = 1; i < 8; i++) m = fmaxf(m, red1[i]);

    float s = 0.0f;
#pragma unroll
    for (int j = 0; j < 32; j++) { v[j] = __expf(v[j] - m); s += v[j]; }
#pragma unroll
    for (int o = 16; o > 0; o >>= 1)
        s += __shfl_xor_sync(0xffffffff, s, o);
    if ((tid & 31) == 0) red2[tid >> 5] = s;
    __syncthreads();
    s = 0.0f;
#pragma unroll
    for (int i = 0; i < 8; i++) s += red2[i];
    const float inv = 1.0f / s;

#pragma unroll
    for (int i = 0; i < 4; i++) {
        uint4 u;
        *(__half2*)&u.x       = __floats2half2_rn(v[i*8+0] * inv, v[i*8+1] * inv);
        *((__half2*)&u.x + 1) = __floats2half2_rn(v[i*8+2] * inv, v[i*8+3] * inv);
        *(__half2*)&u.z       = __floats2half2_rn(v[i*8+4] * inv, v[i*8+5] * inv);
        *((__half2*)&u.z + 1) = __floats2half2_rn(v[i*8+6] * inv, v[i*8+7] * inv);
        po[i * 256 + tid] = u;
    }
}

// fused gate + combine with split gate logits:
// a1 = u + w1, a2 = u + w2; g = sigmoid(sigmoid(a1)-sigmoid(a2));
// out = g*attn1 + (1-g)*attn2
__global__ void __launch_bounds__(256)
combine_kernel(float* __restrict__ out, const float* __restrict__ u,
               const float* __restrict__ w1, const float* __restrict__ w2,
               const float* __restrict__ A1, const float* __restrict__ A2, int n)
{
    int i = blockIdx.x * 256 + threadIdx.x;
    if (i < n) {
        float uu = u[i];
        float s1 = 1.0f / (1.0f + __expf(-(uu + w1[i])));
        float s2 = 1.0f / (1.0f + __expf(-(uu + w2[i])));
        float g  = 1.0f / (1.0f + __expf(-(s1 - s2)));
        out[i] = g * A1[i] + (1.0f - g) * A2[i];
    }
}

// ===========================================================================
extern "C" void kernel_launch(void* const* d_in, const int* in_sizes, int n_in,
                              void* d_out, int out_size)
{
    const float* sp   = (const float*)d_in[0];
    const float* om1  = (const float*)d_in[1];
    const float* om2  = (const float*)d_in[2];
    const float* q_w  = (const float*)d_in[3];
    const float* q_b  = (const float*)d_in[4];
    const float* k1_w = (const float*)d_in[5];
    const float* k1_b = (const float*)d_in[6];
    const float* k2_w = (const float*)d_in[7];
    const float* k2_b = (const float*)d_in[8];
    const float* v_w  = (const float*)d_in[9];
    const float* v_b  = (const float*)d_in[10];
    const float* c1_w = (const float*)d_in[11];
    const float* c1_b = (const float*)d_in[12];
    float* out = (float*)d_out;

    float* base = nullptr;
    cudaGetSymbolAddress((void**)&base, g_scratch);
    float* u     = base + 0 * NC;
    float* w1    = base + 1 * NC;
    float* w2    = base + 2 * NC;
    float* attn1 = base + 3 * NC;
    float* attn2 = base + 4 * NC;
    __half* hb   = (__half*)(base + FLOAT_REGION);
    __half* sph  = hb + 0 * NC;
    __half* om1h = hb + 1 * NC;
    __half* om2h = hb + 2 * NC;
    __half* qh   = hb + 3 * NC;
    __half* k1h  = hb + 4 * NC;
    __half* k2h  = hb + 5 * NC;
    __half* vh   = hb + 6 * NC;
    __half* vTh  = hb + 7 * NC;
    __half* S1   = hb + 8 * NC;
    __half* S2   = S1 + S_ELEMS;
    __half* P1   = S2 + S_ELEMS;
    __half* P2   = P1 + S_ELEMS;
    __half* wts  = P2 + S_ELEMS;
    __half* qwh  = wts;
    __half* k1wh = wts + 262144;
    __half* k2wh = wts + 524288;
    __half* vwh  = wts + 786432;
    __half* c1wh = wts + 1572864;          // [512 x 1024] fp16

    cudaFuncSetAttribute(mma_nt_kernel<float>,
                         cudaFuncAttributeMaxDynamicSharedMemorySize, SMEM_GEMM);
    cudaFuncSetAttribute(mma_nt_kernel<__half>,
                         cudaFuncAttributeMaxDynamicSharedMemorySize, SMEM_GEMM);

    const float scale = 0.044194173824159223f;  // 1/sqrt(512)
    const int elemBlocks = (int)((NC + 255) / 256);

    // (1) fused operand conversion
    convert_all_kernel<<<(CVT_TOTAL + 255) / 256, 256>>>(
        sp, om1, om2, q_w, k1_w, k2_w, v_w, c1_w,
        sph, om1h, om2h, qwh, k1wh, k2wh, vwh, c1wh);

    // (2) q / k1 / k2 projections, one z=3 launch
    {
        GemmBatch bt = {};
        bt.C[0] = qh;  bt.C[1] = k1h; bt.C[2] = k2h;
        bt.A0[0] = sph; bt.A0[1] = om1h; bt.A0[2] = om2h;
        bt.B[0] = qwh; bt.B[1] = k1wh; bt.B[2] = k2wh;
        bt.bias[0] = q_b; bt.bias[1] = k1_b; bt.bias[2] = k2_b;
        mma_nt_kernel<__half><<<dim3(CH / 128, NROWS / 128, 3), 256, SMEM_GEMM>>>(
            bt, CH, 512, 512, 9, 1.0f);
    }

    // (3) v projection (K-concat 1536)
    {
        GemmBatch bt = {};
        bt.C[0] = vh; bt.A0[0] = sph; bt.A1[0] = om1h; bt.A2[0] = om2h;
        bt.B[0] = vwh; bt.bias[0] = v_b;
        mma_nt_kernel<__half><<<dim3(CH / 128, NROWS / 128, 1), 256, SMEM_GEMM>>>(
            bt, CH, 1536, 1536, 9, 1.0f);
    }

    // (4) V transpose
    transpose_h_kernel<<<dim3(CH / 32, NROWS / 32), 256>>>(vTh, vh);

    // (5) S1 = q k1^T, S2 = q k2^T (z=2, fp16 out)
    {
        GemmBatch bt = {};
        bt.C[0] = S1; bt.C[1] = S2;
        bt.A0[0] = qh; bt.A0[1] = qh;
        bt.B[0] = k1h; bt.B[1] = k2h;
        mma_nt_kernel<__half><<<dim3(NROWS / 128, NROWS / 128, 2), 256, SMEM_GEMM>>>(
            bt, NROWS, 512, 512, 9, scale);
    }

    // (6) batched softmax
    softmax_kernel<<<dim3(NROWS, 2), 256>>>(S1, S2, P1, P2);

    // (7) attn1 = P1 vT^T, attn2 = P2 vT^T (z=2, fp32 out)
    {
        GemmBatch bt = {};
        bt.C[0] = attn1; bt.C[1] = attn2;
        bt.A0[0] = P1; bt.A0[1] = P2;
        bt.B[0] = vTh; bt.B[1] = vTh;
        mma_nt_kernel<float><<<dim3(CH / 128, NROWS / 128, 2), 256, SMEM_GEMM>>>(
            bt, CH, NROWS, NROWS, 13, 1.0f);
    }

    // (8) gate logits, split form: u = sp@Wsp^T (+bias), w1 = om1@Wom^T,
    //     w2 = om2@Wom^T — one z=3 launch, K=512, ldb=1024
    {
        GemmBatch bt = {};
        bt.C[0] = u;  bt.C[1] = w1;  bt.C[2] = w2;
        bt.A0[0] = sph; bt.A0[1] = om1h; bt.A0[2] = om2h;
        bt.B[0] = c1wh; bt.B[1] = c1wh + 512; bt.B[2] = c1wh + 512;
        bt.bias[0] = c1_b;
        mma_nt_kernel<float><<<dim3(CH / 128, NROWS / 128, 3), 256, SMEM_GEMM>>>(
            bt, CH, 512, 1024, 9, 1.0f);
    }

    // (9) fused gate + combine
    combine_kernel<<<elemBlocks, 256>>>(out, u, w1, w2, attn1, attn2, (int)NC);
}

// round 11
// speedup vs baseline: 1.4022x; 1.0374x over previous
#include <cuda_runtime.h>
#include <cuda_fp16.h>
#include <cstdint>

#define NROWS 8192
#define CH    512
#define NC    ((size_t)NROWS * CH)          // 4,194,304
#define S_ELEMS ((size_t)NROWS * NROWS)     // 67,108,864

// float region: u,w1,w2,attn1,attn2 (5*NC) + rowsum (2*8192)
// half  region: sph,om1h,om2h,qh,k1h,k2h,vh,vTh (8*NC), S1,S2 (2*S_ELEMS), weights
#define FLOAT_REGION (5 * NC + 2 * NROWS)
#define HALF_REGION  (8 * NC + 2 * S_ELEMS + 2097152)
__device__ float g_scratch[FLOAT_REGION + HALF_REGION / 2 + 1024];

// ===========================================================================
// helpers
// ===========================================================================
__device__ __forceinline__ uint32_t smem_u32(const void* p) {
    uint32_t a;
    asm("{ .reg .u64 t; cvta.to.shared.u64 t, %1; cvt.u32.u64 %0, t; }"
        : "=r"(a) : "l"(p));
    return a;
}
__device__ __forceinline__ void cp16(uint32_t dst, const void* src) {
    asm volatile("cp.async.cg.shared.global [%0], [%1], 16;" :: "r"(dst), "l"(src));
}
__device__ __forceinline__ void ldmx4(uint32_t* r, uint32_t addr) {
    asm volatile("ldmatrix.sync.aligned.m8n8.x4.shared.b16 {%0,%1,%2,%3}, [%4];"
                 : "=r"(r[0]), "=r"(r[1]), "=r"(r[2]), "=r"(r[3]) : "r"(addr));
}
__device__ __forceinline__ void mma_f16(float* d, const uint32_t* a,
                                        uint32_t b0, uint32_t b1) {
    asm volatile(
        "mma.sync.aligned.m16n8k16.row.col.f32.f16.f16.f32 "
        "{%0,%1,%2,%3}, {%4,%5,%6,%7}, {%8,%9}, {%0,%1,%2,%3};"
        : "+f"(d[0]), "+f"(d[1]), "+f"(d[2]), "+f"(d[3])
        : "r"(a[0]), "r"(a[1]), "r"(a[2]), "r"(a[3]), "r"(b0), "r"(b1));
}
// 16B-chunk swizzle within a 64B row -> conflict-free ldmatrix + cp.async
__device__ __forceinline__ uint32_t sw16(int r, int c) {
    return (uint32_t)((c ^ ((r >> 1) & 3)) * 16);
}

// Up to 3 problem instances selected by blockIdx.z
struct GemmBatch {
    void*         C[3];
    const __half* A0[3];
    const __half* A1[3];     // K-concat segment 2 (nullptr if none)
    const __half* A2[3];     // K-concat segment 3
    const __half* B[3];
    const float*  bias[3];
    float*        rs_out[3]; // fp16 out + exp epilogue + row-sum atomics
    const float*  rs_in[3];  // fp32 out: multiply rows by 1/rs_in[row]
};

// ===========================================================================
// fp16 NT GEMM, tile 128x128, BK=32, 4-stage cp.async, 256 threads
// (8 warps 4m x 2n, per-warp 32x64), 2 CTAs/SM.  (R7 engine, unchanged.)
// Epilogue modes:
//   OutT=half,  rs_out != 0 : C = exp(acc*scale) (fp16), atomicAdd row sums
//   OutT=half,  rs_out == 0 : C = acc*scale + bias (fp16, coalesced staged)
//   OutT=float, rs_in  != 0 : C = (acc*scale) / rs_in[row]
//   OutT=float, rs_in  == 0 : C = acc*scale + bias
// ===========================================================================
#define STAGES   4
#define A_TILE_B 8192                  // 128 rows * 64B
#define STAGE_B  16384
#define SMEM_GEMM (STAGES * STAGE_B)   // 65536

template <typename OutT>
__global__ void __launch_bounds__(256, 2)
mma_nt_kernel(GemmBatch bt, int Nfull, int K, int ldb, int seg_shift, float scale)
{
    const int z = blockIdx.z;
    OutT* C           = (OutT*)bt.C[z];
    const __half* A0  = bt.A0[z];
    const __half* A1  = bt.A1[z];
    const __half* A2  = bt.A2[z];
    const __half* B   = bt.B[z];
    const float* bias = bt.bias[z];
    float* rs_out     = bt.rs_out[z];
    const float* rs_in = bt.rs_in[z];

    extern __shared__ char sm[];
    const uint32_t sbase = smem_u32(sm);
    const int tid  = threadIdx.x;
    const int warp = tid >> 5;
    const int lane = tid & 31;
    const int wm   = warp >> 1;          // 0..3
    const int wn   = warp & 1;           // 0..1
    const int m0   = blockIdx.y * 128;
    const int n0   = blockIdx.x * 128;
    const int nch  = K >> 5;
    const int segmask = (1 << seg_shift) - 1;

    const int lr = tid >> 1;
    const int lc0 = (tid & 1) * 2;

    auto issue = [&](int c) {
        const int kb  = c << 5;
        const int seg = kb >> seg_shift;
        const __half* Asrc = (seg == 0) ? A0 : ((seg == 1) ? A1 : A2);
        const __half* ap = Asrc + (((size_t)(m0 + lr)) << seg_shift) + (kb & segmask);
        const __half* bp = B + (size_t)(n0 + lr) * ldb + kb;
        const uint32_t st = sbase + (c % STAGES) * STAGE_B + lr * 64;
#pragma unroll
        for (int j = 0; j < 2; j++) {
            const int ch = lc0 + j;
            cp16(st + sw16(lr, ch), ap + ch * 8);
            cp16(st + A_TILE_B + sw16(lr, ch), bp + ch * 8);
        }
        asm volatile("cp.async.commit_group;" ::: "memory");
    };

    float acc[2][8][4];
#pragma unroll
    for (int mt = 0; mt < 2; mt++)
#pragma unroll
        for (int nt = 0; nt < 8; nt++)
#pragma unroll
            for (int r = 0; r < 4; r++) acc[mt][nt][r] = 0.0f;

    issue(0); issue(1); issue(2);

    const int l15 = lane & 15;
    const int lhi = lane >> 4;
    uint32_t aoff[2][2], boff[4][2];
#pragma unroll
    for (int mt = 0; mt < 2; mt++)
#pragma unroll
        for (int ks = 0; ks < 2; ks++) {
            const int r = wm * 32 + mt * 16 + l15;
            aoff[mt][ks] = (uint32_t)r * 64 + sw16(r, 2 * ks + lhi);
        }
#pragma unroll
    for (int np = 0; np < 4; np++)
#pragma unroll
        for (int ks = 0; ks < 2; ks++) {
            const int r = wn * 64 + np * 16 + l15;
            boff[np][ks] = A_TILE_B + (uint32_t)r * 64 + sw16(r, 2 * ks + lhi);
        }

    for (int c = 0; c < nch; c++) {
        asm volatile("cp.async.wait_group %0;" :: "n"(2) : "memory");
        __syncthreads();
        if (c + 3 < nch) issue(c + 3);
        else asm volatile("cp.async.commit_group;" ::: "memory");

        const uint32_t st = sbase + (c % STAGES) * STAGE_B;

        uint32_t af0[2][4], af1[2][4], bf[4][4];
        ldmx4(af0[0], st + aoff[0][0]);
        ldmx4(af0[1], st + aoff[1][0]);
        ldmx4(af1[0], st + aoff[0][1]);
        ldmx4(af1[1], st + aoff[1][1]);
#pragma unroll
        for (int np = 0; np < 4; np++) ldmx4(bf[np], st + boff[np][0]);
#pragma unroll
        for (int mt = 0; mt < 2; mt++)
#pragma unroll
            for (int np = 0; np < 4; np++) {
                mma_f16(acc[mt][2 * np],     af0[mt], bf[np][0], bf[np][2]);
                mma_f16(acc[mt][2 * np + 1], af0[mt], bf[np][1], bf[np][3]);
            }
#pragma unroll
        for (int np = 0; np < 4; np++) ldmx4(bf[np], st + boff[np][1]);
#pragma unroll
        for (int mt = 0; mt < 2; mt++)
#pragma unroll
            for (int np = 0; np < 4; np++) {
                mma_f16(acc[mt][2 * np],     af1[mt], bf[np][0], bf[np][2]);
                mma_f16(acc[mt][2 * np + 1], af1[mt], bf[np][1], bf[np][3]);
            }
    }

    // ------------------------------ epilogue -------------------------------
    const int frow = lane >> 2;
    const int fcol = lane & 3;
    if constexpr (sizeof(OutT) == 2) {
        const bool do_exp = (rs_out != nullptr);
        __syncthreads();                    // done reading pipeline stages
        __half* sbuf = (__half*)sm;
        float rpart[2][2] = {{0.0f, 0.0f}, {0.0f, 0.0f}};
#pragma unroll
        for (int mt = 0; mt < 2; mt++) {
            const int row = wm * 32 + mt * 16 + frow;
#pragma unroll
            for (int nt = 0; nt < 8; nt++) {
                const int col = n0 + wn * 64 + nt * 8 + fcol * 2;
                const int lcol = wn * 64 + nt * 8 + fcol * 2;
                float x0 = acc[mt][nt][0] * scale;
                float x1 = acc[mt][nt][1] * scale;
                float x2 = acc[mt][nt][2] * scale;
                float x3 = acc[mt][nt][3] * scale;
                if (do_exp) {
                    x0 = __expf(fminf(x0, 11.0f));
                    x1 = __expf(fminf(x1, 11.0f));
                    x2 = __expf(fminf(x2, 11.0f));
                    x3 = __expf(fminf(x3, 11.0f));
                    rpart[mt][0] += x0 + x1;
                    rpart[mt][1] += x2 + x3;
                } else if (bias != nullptr) {
                    float b0 = bias[col], b1 = bias[col + 1];
                    x0 += b0; x1 += b1; x2 += b0; x3 += b1;
                }
                *(__half2*)(sbuf + (size_t)row * 136 + lcol) =
                    __floats2half2_rn(x0, x1);
                *(__half2*)(sbuf + (size_t)(row + 8) * 136 + lcol) =
                    __floats2half2_rn(x2, x3);
            }
        }
        __syncthreads();
        // coalesced streamout: thread t -> row t/2, 64-half run
        const int orow  = tid >> 1;
        const int obase = (tid & 1) * 64;
        const uint4* srow = (const uint4*)(sbuf + (size_t)orow * 136 + obase);
        uint4* crow = (uint4*)((__half*)C + (size_t)(m0 + orow) * Nfull + n0 + obase);
#pragma unroll
        for (int j = 0; j < 8; j++) crow[j] = srow[j];
        if (do_exp) {
            // reduce partial row sums across the 4 fcol lanes, then atomicAdd
#pragma unroll
            for (int mt = 0; mt < 2; mt++)
#pragma unroll
                for (int h = 0; h < 2; h++) {
                    float v = rpart[mt][h];
                    v += __shfl_xor_sync(0xffffffff, v, 1);
                    v += __shfl_xor_sync(0xffffffff, v, 2);
                    if (fcol == 0)
                        atomicAdd(&rs_out[m0 + wm * 32 + mt * 16 + h * 8 + frow], v);
                }
        }
    } else {
#pragma unroll
        for (int mt = 0; mt < 2; mt++) {
            const int row = m0 + wm * 32 + mt * 16 + frow;
            float s0 = 1.0f, s1 = 1.0f;
            if (rs_in != nullptr) {
                s0 = 1.0f / rs_in[row];
                s1 = 1.0f / rs_in[row + 8];
            }
#pragma unroll
            for (int nt = 0; nt < 8; nt++) {
                const int col = n0 + wn * 64 + nt * 8 + fcol * 2;
                float b0 = 0.0f, b1 = 0.0f;
                if (bias != nullptr) { b0 = bias[col]; b1 = bias[col + 1]; }
                *(float2*)((float*)C + (size_t)row * Nfull + col) =
                    make_float2(acc[mt][nt][0] * scale * s0 + b0,
                                acc[mt][nt][1] * scale * s0 + b1);
                *(float2*)((float*)C + (size_t)(row + 8) * Nfull + col) =
                    make_float2(acc[mt][nt][2] * scale * s1 + b0,
                                acc[mt][nt][3] * scale * s1 + b1);
            }
        }
    }
}

// ===========================================================================
// zero rowsum accumulators (2 * 8192 floats)
// ===========================================================================
__global__ void __launch_bounds__(256)
zero_kernel(float* __restrict__ p, int n)
{
    int i = blockIdx.x * 256 + threadIdx.x;
    if (i < n) p[i] = 0.0f;
}

// ===========================================================================
// Fused fp32->fp16 conversion for all 8 operands
// ===========================================================================
#define SEG_IN  ((int)(NC / 4))
#define SEG_W5  65536
#define SEG_VW  196608
#define SEG_CW  131072
#define CVT_TOTAL (3 * SEG_IN + 3 * SEG_W5 + SEG_VW + SEG_CW)

__global__ void __launch_bounds__(256)
convert_all_kernel(const float* __restrict__ sp, const float* __restrict__ om1,
                   const float* __restrict__ om2, const float* __restrict__ qw,
                   const float* __restrict__ k1w, const float* __restrict__ k2w,
                   const float* __restrict__ vw, const float* __restrict__ cw,
                   __half* __restrict__ sph, __half* __restrict__ om1h,
                   __half* __restrict__ om2h, __half* __restrict__ qwh,
                   __half* __restrict__ k1wh, __half* __restrict__ k2wh,
                   __half* __restrict__ vwh, __half* __restrict__ cwh)
{
    int i = blockIdx.x * 256 + threadIdx.x;
    if (i >= CVT_TOTAL) return;
    const float* src; __half* dst; int off = i;
    if (off < SEG_IN) { src = sp; dst = sph; }
    else if ((off -= SEG_IN) < SEG_IN) { src = om1; dst = om1h; }
    else if ((off -= SEG_IN) < SEG_IN) { src = om2; dst = om2h; }
    else if ((off -= SEG_IN) < SEG_W5) { src = qw; dst = qwh; }
    else if ((off -= SEG_W5) < SEG_W5) { src = k1w; dst = k1wh; }
    else if ((off -= SEG_W5) < SEG_W5) { src = k2w; dst = k2wh; }
    else if ((off -= SEG_W5) < SEG_VW) { src = vw; dst = vwh; }
    else { off -= SEG_VW; src = cw; dst = cwh; }
    float4 x = ((const float4*)src)[off];
    ((__half2*)dst)[2 * off]     = __floats2half2_rn(x.x, x.y);
    ((__half2*)dst)[2 * off + 1] = __floats2half2_rn(x.z, x.w);
}

__global__ void __launch_bounds__(256)
transpose_h_kernel(__half* __restrict__ out, const __half* __restrict__ in)
{
    __shared__ __half tile[32][34];
    const int tx = threadIdx.x & 31;
    const int ty = threadIdx.x >> 5;
    const int x0 = blockIdx.x * 32;
    const int y0 = blockIdx.y * 32;
#pragma unroll
    for (int j = 0; j < 32; j += 8)
        tile[ty + j][tx] = in[(size_t)(y0 + ty + j) * CH + x0 + tx];
    __syncthreads();
#pragma unroll
    for (int j = 0; j < 32; j += 8)
        out[(size_t)(x0 + ty + j) * NROWS + y0 + tx] = tile[tx][ty + j];
}

// fused gate + combine with split gate logits:
// a1 = u + w1, a2 = u + w2; g = sigmoid(sigmoid(a1)-sigmoid(a2));
// out = g*attn1 + (1-g)*attn2
__global__ void __launch_bounds__(256)
combine_kernel(float* __restrict__ out, const float* __restrict__ u,
               const float* __restrict__ w1, const float* __restrict__ w2,
               const float* __restrict__ A1, const float* __restrict__ A2, int n)
{
    int i = blockIdx.x * 256 + threadIdx.x;
    if (i < n) {
        float uu = u[i];
        float s1 = 1.0f / (1.0f + __expf(-(uu + w1[i])));
        float s2 = 1.0f / (1.0f + __expf(-(uu + w2[i])));
        float g  = 1.0f / (1.0f + __expf(-(s1 - s2)));
        out[i] = g * A1[i] + (1.0f - g) * A2[i];
    }
}

// ===========================================================================
extern "C" void kernel_launch(void* const* d_in, const int* in_sizes, int n_in,
                              void* d_out, int out_size)
{
    const float* sp   = (const float*)d_in[0];
    const float* om1  = (const float*)d_in[1];
    const float* om2  = (const float*)d_in[2];
    const float* q_w  = (const float*)d_in[3];
    const float* q_b  = (const float*)d_in[4];
    const float* k1_w = (const float*)d_in[5];
    const float* k1_b = (const float*)d_in[6];
    const float* k2_w = (const float*)d_in[7];
    const float* k2_b = (const float*)d_in[8];
    const float* v_w  = (const float*)d_in[9];
    const float* v_b  = (const float*)d_in[10];
    const float* c1_w = (const float*)d_in[11];
    const float* c1_b = (const float*)d_in[12];
    float* out = (float*)d_out;

    float* base = nullptr;
    cudaGetSymbolAddress((void**)&base, g_scratch);
    float* u     = base + 0 * NC;
    float* w1    = base + 1 * NC;
    float* w2    = base + 2 * NC;
    float* attn1 = base + 3 * NC;
    float* attn2 = base + 4 * NC;
    float* rsum1 = base + 5 * NC;           // 8192
    float* rsum2 = rsum1 + NROWS;           // 8192
    __half* hb   = (__half*)(base + FLOAT_REGION);
    __half* sph  = hb + 0 * NC;
    __half* om1h = hb + 1 * NC;
    __half* om2h = hb + 2 * NC;
    __half* qh   = hb + 3 * NC;
    __half* k1h  = hb + 4 * NC;
    __half* k2h  = hb + 5 * NC;
    __half* vh   = hb + 6 * NC;
    __half* vTh  = hb + 7 * NC;
    __half* S1   = hb + 8 * NC;             // holds E1 = exp(q k1^T * scale)
    __half* S2   = S1 + S_ELEMS;            // holds E2
    __half* wts  = S2 + S_ELEMS;
    __half* qwh  = wts;
    __half* k1wh = wts + 262144;
    __half* k2wh = wts + 524288;
    __half* vwh  = wts + 786432;
    __half* c1wh = wts + 1572864;           // [512 x 1024] fp16

    cudaFuncSetAttribute(mma_nt_kernel<float>,
                         cudaFuncAttributeMaxDynamicSharedMemorySize, SMEM_GEMM);
    cudaFuncSetAttribute(mma_nt_kernel<__half>,
                         cudaFuncAttributeMaxDynamicSharedMemorySize, SMEM_GEMM);

    const float scale = 0.044194173824159223f;  // 1/sqrt(512)
    const int elemBlocks = (int)((NC + 255) / 256);

    // (0) zero the rowsum accumulators
    zero_kernel<<<(2 * NROWS + 255) / 256, 256>>>(rsum1, 2 * NROWS);

    // (1) fused operand conversion
    convert_all_kernel<<<(CVT_TOTAL + 255) / 256, 256>>>(
        sp, om1, om2, q_w, k1_w, k2_w, v_w, c1_w,
        sph, om1h, om2h, qwh, k1wh, k2wh, vwh, c1wh);

    // (2) q / k1 / k2 projections, one z=3 launch
    {
        GemmBatch bt = {};
        bt.C[0] = qh;  bt.C[1] = k1h; bt.C[2] = k2h;
        bt.A0[0] = sph; bt.A0[1] = om1h; bt.A0[2] = om2h;
        bt.B[0] = qwh; bt.B[1] = k1wh; bt.B[2] = k2wh;
        bt.bias[0] = q_b; bt.bias[1] = k1_b; bt.bias[2] = k2_b;
        mma_nt_kernel<__half><<<dim3(CH / 128, NROWS / 128, 3), 256, SMEM_GEMM>>>(
            bt, CH, 512, 512, 9, 1.0f);
    }

    // (3) v projection (K-concat 1536)
    {
        GemmBatch bt = {};
        bt.C[0] = vh; bt.A0[0] = sph; bt.A1[0] = om1h; bt.A2[0] = om2h;
        bt.B[0] = vwh; bt.bias[0] = v_b;
        mma_nt_kernel<__half><<<dim3(CH / 128, NROWS / 128, 1), 256, SMEM_GEMM>>>(
            bt, CH, 1536, 1536, 9, 1.0f);
    }

    // (4) V transpose
    transpose_h_kernel<<<dim3(CH / 32, NROWS / 32), 256>>>(vTh, vh);

    // (5) E1 = exp(q k1^T * scale), E2 = exp(q k2^T * scale) with row-sum
    //     atomics (z=2, fp16 out) — softmax normalization deferred to PV
    {
        GemmBatch bt = {};
        bt.C[0] = S1; bt.C[1] = S2;
        bt.A0[0] = qh; bt.A0[1] = qh;
        bt.B[0] = k1h; bt.B[1] = k2h;
        bt.rs_out[0] = rsum1; bt.rs_out[1] = rsum2;
        mma_nt_kernel<__half><<<dim3(NROWS / 128, NROWS / 128, 2), 256, SMEM_GEMM>>>(
            bt, NROWS, 512, 512, 9, scale);
    }

    // (6) attn1 = (E1 vT^T)/rowsum1, attn2 = (E2 vT^T)/rowsum2 (z=2, fp32 out)
    {
        GemmBatch bt = {};
        bt.C[0] = attn1; bt.C[1] = attn2;
        bt.A0[0] = S1; bt.A0[1] = S2;
        bt.B[0] = vTh; bt.B[1] = vTh;
        bt.rs_in[0] = rsum1; bt.rs_in[1] = rsum2;
        mma_nt_kernel<float><<<dim3(CH / 128, NROWS / 128, 2), 256, SMEM_GEMM>>>(
            bt, CH, NROWS, NROWS, 13, 1.0f);
    }

    // (7) gate logits, split form: u = sp@Wsp^T (+bias), w1 = om1@Wom^T,
    //     w2 = om2@Wom^T — one z=3 launch, K=512, ldb=1024
    {
        GemmBatch bt = {};
        bt.C[0] = u;  bt.C[1] = w1;  bt.C[2] = w2;
        bt.A0[0] = sph; bt.A0[1] = om1h; bt.A0[2] = om2h;
        bt.B[0] = c1wh; bt.B[1] = c1wh + 512; bt.B[2] = c1wh + 512;
        bt.bias[0] = c1_b;
        mma_nt_kernel<float><<<dim3(CH / 128, NROWS / 128, 3), 256, SMEM_GEMM>>>(
            bt, CH, 512, 1024, 9, 1.0f);
    }

    // (8) fused gate + combine
    combine_kernel<<<elemBlocks, 256>>>(out, u, w1, w2, attn1, attn2, (int)NC);
}

// round 12
// speedup vs baseline: 1.4049x; 1.0019x over previous
#include <cuda_runtime.h>
#include <cuda_fp16.h>
#include <cstdint>

#define NROWS 8192
#define CH    512
#define NC    ((size_t)NROWS * CH)          // 4,194,304
#define S_ELEMS ((size_t)NROWS * NROWS)     // 67,108,864

// float region: u,w1,w2,attn1,attn2 (5*NC) + rowsum (2*8192)
// half  region: sph,om1h,om2h,qh,k1h,k2h,vh,vTh (8*NC), S1,S2 (2*S_ELEMS), weights
#define FLOAT_REGION (5 * NC + 2 * NROWS)
#define HALF_REGION  (8 * NC + 2 * S_ELEMS + 2097152)
__device__ float g_scratch[FLOAT_REGION + HALF_REGION / 2 + 1024];

// ===========================================================================
// helpers
// ===========================================================================
__device__ __forceinline__ uint32_t smem_u32(const void* p) {
    uint32_t a;
    asm("{ .reg .u64 t; cvta.to.shared.u64 t, %1; cvt.u32.u64 %0, t; }"
        : "=r"(a) : "l"(p));
    return a;
}
__device__ __forceinline__ void cp16(uint32_t dst, const void* src) {
    asm volatile("cp.async.cg.shared.global [%0], [%1], 16;" :: "r"(dst), "l"(src));
}
__device__ __forceinline__ void ldmx4(uint32_t* r, uint32_t addr) {
    asm volatile("ldmatrix.sync.aligned.m8n8.x4.shared.b16 {%0,%1,%2,%3}, [%4];"
                 : "=r"(r[0]), "=r"(r[1]), "=r"(r[2]), "=r"(r[3]) : "r"(addr));
}
__device__ __forceinline__ void mma_f16(float* d, const uint32_t* a,
                                        uint32_t b0, uint32_t b1) {
    asm volatile(
        "mma.sync.aligned.m16n8k16.row.col.f32.f16.f16.f32 "
        "{%0,%1,%2,%3}, {%4,%5,%6,%7}, {%8,%9}, {%0,%1,%2,%3};"
        : "+f"(d[0]), "+f"(d[1]), "+f"(d[2]), "+f"(d[3])
        : "r"(a[0]), "r"(a[1]), "r"(a[2]), "r"(a[3]), "r"(b0), "r"(b1));
}
// 16B-chunk swizzle within a 64B row -> conflict-free ldmatrix + cp.async
__device__ __forceinline__ uint32_t sw16(int r, int c) {
    return (uint32_t)((c ^ ((r >> 1) & 3)) * 16);
}

// Up to 3 problem instances selected by blockIdx.z
struct GemmBatch {
    void*         C[3];
    const __half* A0[3];
    const __half* A1[3];     // K-concat segment 2 (nullptr if none)
    const __half* A2[3];     // K-concat segment 3
    const __half* B[3];
    const float*  bias[3];
    float*        rs_out[3]; // fp16 out + exp epilogue + row-sum atomics
    const float*  rs_in[3];  // fp32 out: multiply rows by 1/rs_in[row]
};

// ===========================================================================
// fp16 NT GEMM, tile 128x128, BK=32, 4-stage cp.async, 256 threads
// (8 warps 4m x 2n, per-warp 32x64), 2 CTAs/SM.  (R7 engine, unchanged.)
// Epilogue modes:
//   OutT=half,  rs_out != 0 : C = exp(acc*scale) (fp16, streaming store),
//                             atomicAdd row sums
//   OutT=half,  rs_out == 0 : C = acc*scale + bias (fp16, streaming store)
//   OutT=float, rs_in  != 0 : C = (acc*scale) / rs_in[row]
//   OutT=float, rs_in  == 0 : C = acc*scale + bias
// For S-shaped launches (gridDim.x == 64) CTAs are re-rastered into 8-m-tile
// super-rows so each scheduling wave touches a compact L2 working set.
// ===========================================================================
#define STAGES   4
#define A_TILE_B 8192                  // 128 rows * 64B
#define STAGE_B  16384
#define SMEM_GEMM (STAGES * STAGE_B)   // 65536

template <typename OutT>
__global__ void __launch_bounds__(256, 2)
mma_nt_kernel(GemmBatch bt, int Nfull, int K, int ldb, int seg_shift, float scale)
{
    const int z = blockIdx.z;
    OutT* C           = (OutT*)bt.C[z];
    const __half* A0  = bt.A0[z];
    const __half* A1  = bt.A1[z];
    const __half* A2  = bt.A2[z];
    const __half* B   = bt.B[z];
    const float* bias = bt.bias[z];
    float* rs_out     = bt.rs_out[z];
    const float* rs_in = bt.rs_in[z];

    extern __shared__ char sm[];
    const uint32_t sbase = smem_u32(sm);
    const int tid  = threadIdx.x;
    const int warp = tid >> 5;
    const int lane = tid & 31;
    const int wm   = warp >> 1;          // 0..3
    const int wn   = warp & 1;           // 0..1

    // super-tile rasterization for square (64x64) S launches
    int bx = blockIdx.x, by = blockIdx.y;
    if (gridDim.x == 64) {
        const int t = by * 64 + bx;      // 0..4095
        const int g = t >> 9;            // super-row of 8 m-tiles
        const int r = t & 511;
        by = g * 8 + (r & 7);
        bx = r >> 3;
    }
    const int m0   = by * 128;
    const int n0   = bx * 128;
    const int nch  = K >> 5;
    const int segmask = (1 << seg_shift) - 1;

    const int lr = tid >> 1;
    const int lc0 = (tid & 1) * 2;

    auto issue = [&](int c) {
        const int kb  = c << 5;
        const int seg = kb >> seg_shift;
        const __half* Asrc = (seg == 0) ? A0 : ((seg == 1) ? A1 : A2);
        const __half* ap = Asrc + (((size_t)(m0 + lr)) << seg_shift) + (kb & segmask);
        const __half* bp = B + (size_t)(n0 + lr) * ldb + kb;
        const uint32_t st = sbase + (c % STAGES) * STAGE_B + lr * 64;
#pragma unroll
        for (int j = 0; j < 2; j++) {
            const int ch = lc0 + j;
            cp16(st + sw16(lr, ch), ap + ch * 8);
            cp16(st + A_TILE_B + sw16(lr, ch), bp + ch * 8);
        }
        asm volatile("cp.async.commit_group;" ::: "memory");
    };

    float acc[2][8][4];
#pragma unroll
    for (int mt = 0; mt < 2; mt++)
#pragma unroll
        for (int nt = 0; nt < 8; nt++)
#pragma unroll
            for (int r = 0; r < 4; r++) acc[mt][nt][r] = 0.0f;

    issue(0); issue(1); issue(2);

    const int l15 = lane & 15;
    const int lhi = lane >> 4;
    uint32_t aoff[2][2], boff[4][2];
#pragma unroll
    for (int mt = 0; mt < 2; mt++)
#pragma unroll
        for (int ks = 0; ks < 2; ks++) {
            const int r = wm * 32 + mt * 16 + l15;
            aoff[mt][ks] = (uint32_t)r * 64 + sw16(r, 2 * ks + lhi);
        }
#pragma unroll
    for (int np = 0; np < 4; np++)
#pragma unroll
        for (int ks = 0; ks < 2; ks++) {
            const int r = wn * 64 + np * 16 + l15;
            boff[np][ks] = A_TILE_B + (uint32_t)r * 64 + sw16(r, 2 * ks + lhi);
        }

    for (int c = 0; c < nch; c++) {
        asm volatile("cp.async.wait_group %0;" :: "n"(2) : "memory");
        __syncthreads();
        if (c + 3 < nch) issue(c + 3);
        else asm volatile("cp.async.commit_group;" ::: "memory");

        const uint32_t st = sbase + (c % STAGES) * STAGE_B;

        uint32_t af0[2][4], af1[2][4], bf[4][4];
        ldmx4(af0[0], st + aoff[0][0]);
        ldmx4(af0[1], st + aoff[1][0]);
        ldmx4(af1[0], st + aoff[0][1]);
        ldmx4(af1[1], st + aoff[1][1]);
#pragma unroll
        for (int np = 0; np < 4; np++) ldmx4(bf[np], st + boff[np][0]);
#pragma unroll
        for (int mt = 0; mt < 2; mt++)
#pragma unroll
            for (int np = 0; np < 4; np++) {
                mma_f16(acc[mt][2 * np],     af0[mt], bf[np][0], bf[np][2]);
                mma_f16(acc[mt][2 * np + 1], af0[mt], bf[np][1], bf[np][3]);
            }
#pragma unroll
        for (int np = 0; np < 4; np++) ldmx4(bf[np], st + boff[np][1]);
#pragma unroll
        for (int mt = 0; mt < 2; mt++)
#pragma unroll
            for (int np = 0; np < 4; np++) {
                mma_f16(acc[mt][2 * np],     af1[mt], bf[np][0], bf[np][2]);
                mma_f16(acc[mt][2 * np + 1], af1[mt], bf[np][1], bf[np][3]);
            }
    }

    // ------------------------------ epilogue -------------------------------
    const int frow = lane >> 2;
    const int fcol = lane & 3;
    if constexpr (sizeof(OutT) == 2) {
        const bool do_exp = (rs_out != nullptr);
        __syncthreads();                    // done reading pipeline stages
        __half* sbuf = (__half*)sm;
        float rpart[2][2] = {{0.0f, 0.0f}, {0.0f, 0.0f}};
#pragma unroll
        for (int mt = 0; mt < 2; mt++) {
            const int row = wm * 32 + mt * 16 + frow;
#pragma unroll
            for (int nt = 0; nt < 8; nt++) {
                const int col = n0 + wn * 64 + nt * 8 + fcol * 2;
                const int lcol = wn * 64 + nt * 8 + fcol * 2;
                float x0 = acc[mt][nt][0] * scale;
                float x1 = acc[mt][nt][1] * scale;
                float x2 = acc[mt][nt][2] * scale;
                float x3 = acc[mt][nt][3] * scale;
                if (do_exp) {
                    x0 = __expf(fminf(x0, 11.0f));
                    x1 = __expf(fminf(x1, 11.0f));
                    x2 = __expf(fminf(x2, 11.0f));
                    x3 = __expf(fminf(x3, 11.0f));
                    rpart[mt][0] += x0 + x1;
                    rpart[mt][1] += x2 + x3;
                } else if (bias != nullptr) {
                    float b0 = bias[col], b1 = bias[col + 1];
                    x0 += b0; x1 += b1; x2 += b0; x3 += b1;
                }
                *(__half2*)(sbuf + (size_t)row * 136 + lcol) =
                    __floats2half2_rn(x0, x1);
                *(__half2*)(sbuf + (size_t)(row + 8) * 136 + lcol) =
                    __floats2half2_rn(x2, x3);
            }
        }
        __syncthreads();
        // coalesced STREAMING streamout: thread t -> row t/2, 64-half run.
        // st.global.cs keeps the 268MB of S/E writes from thrashing L2.
        const int orow  = tid >> 1;
        const int obase = (tid & 1) * 64;
        const uint4* srow = (const uint4*)(sbuf + (size_t)orow * 136 + obase);
        uint4* crow = (uint4*)((__half*)C + (size_t)(m0 + orow) * Nfull + n0 + obase);
#pragma unroll
        for (int j = 0; j < 8; j++) __stcs(&crow[j], srow[j]);
        if (do_exp) {
            // reduce partial row sums across the 4 fcol lanes, then atomicAdd
#pragma unroll
            for (int mt = 0; mt < 2; mt++)
#pragma unroll
                for (int h = 0; h < 2; h++) {
                    float v = rpart[mt][h];
                    v += __shfl_xor_sync(0xffffffff, v, 1);
                    v += __shfl_xor_sync(0xffffffff, v, 2);
                    if (fcol == 0)
                        atomicAdd(&rs_out[m0 + wm * 32 + mt * 16 + h * 8 + frow], v);
                }
        }
    } else {
#pragma unroll
        for (int mt = 0; mt < 2; mt++) {
            const int row = m0 + wm * 32 + mt * 16 + frow;
            float s0 = 1.0f, s1 = 1.0f;
            if (rs_in != nullptr) {
                s0 = 1.0f / rs_in[row];
                s1 = 1.0f / rs_in[row + 8];
            }
#pragma unroll
            for (int nt = 0; nt < 8; nt++) {
                const int col = n0 + wn * 64 + nt * 8 + fcol * 2;
                float b0 = 0.0f, b1 = 0.0f;
                if (bias != nullptr) { b0 = bias[col]; b1 = bias[col + 1]; }
                *(float2*)((float*)C + (size_t)row * Nfull + col) =
                    make_float2(acc[mt][nt][0] * scale * s0 + b0,
                                acc[mt][nt][1] * scale * s0 + b1);
                *(float2*)((float*)C + (size_t)(row + 8) * Nfull + col) =
                    make_float2(acc[mt][nt][2] * scale * s1 + b0,
                                acc[mt][nt][3] * scale * s1 + b1);
            }
        }
    }
}

// ===========================================================================
// zero rowsum accumulators (2 * 8192 floats)
// ===========================================================================
__global__ void __launch_bounds__(256)
zero_kernel(float* __restrict__ p, int n)
{
    int i = blockIdx.x * 256 + threadIdx.x;
    if (i < n) p[i] = 0.0f;
}

// ===========================================================================
// Fused fp32->fp16 conversion for all 8 operands
// ===========================================================================
#define SEG_IN  ((int)(NC / 4))
#define SEG_W5  65536
#define SEG_VW  196608
#define SEG_CW  131072
#define CVT_TOTAL (3 * SEG_IN + 3 * SEG_W5 + SEG_VW + SEG_CW)

__global__ void __launch_bounds__(256)
convert_all_kernel(const float* __restrict__ sp, const float* __restrict__ om1,
                   const float* __restrict__ om2, const float* __restrict__ qw,
                   const float* __restrict__ k1w, const float* __restrict__ k2w,
                   const float* __restrict__ vw, const float* __restrict__ cw,
                   __half* __restrict__ sph, __half* __restrict__ om1h,
                   __half* __restrict__ om2h, __half* __restrict__ qwh,
                   __half* __restrict__ k1wh, __half* __restrict__ k2wh,
                   __half* __restrict__ vwh, __half* __restrict__ cwh)
{
    int i = blockIdx.x * 256 + threadIdx.x;
    if (i >= CVT_TOTAL) return;
    const float* src; __half* dst; int off = i;
    if (off < SEG_IN) { src = sp; dst = sph; }
    else if ((off -= SEG_IN) < SEG_IN) { src = om1; dst = om1h; }
    else if ((off -= SEG_IN) < SEG_IN) { src = om2; dst = om2h; }
    else if ((off -= SEG_IN) < SEG_W5) { src = qw; dst = qwh; }
    else if ((off -= SEG_W5) < SEG_W5) { src = k1w; dst = k1wh; }
    else if ((off -= SEG_W5) < SEG_W5) { src = k2w; dst = k2wh; }
    else if ((off -= SEG_W5) < SEG_VW) { src = vw; dst = vwh; }
    else { off -= SEG_VW; src = cw; dst = cwh; }
    float4 x = ((const float4*)src)[off];
    ((__half2*)dst)[2 * off]     = __floats2half2_rn(x.x, x.y);
    ((__half2*)dst)[2 * off + 1] = __floats2half2_rn(x.z, x.w);
}

__global__ void __launch_bounds__(256)
transpose_h_kernel(__half* __restrict__ out, const __half* __restrict__ in)
{
    __shared__ __half tile[32][34];
    const int tx = threadIdx.x & 31;
    const int ty = threadIdx.x >> 5;
    const int x0 = blockIdx.x * 32;
    const int y0 = blockIdx.y * 32;
#pragma unroll
    for (int j = 0; j < 32; j += 8)
        tile[ty + j][tx] = in[(size_t)(y0 + ty + j) * CH + x0 + tx];
    __syncthreads();
#pragma unroll
    for (int j = 0; j < 32; j += 8)
        out[(size_t)(x0 + ty + j) * NROWS + y0 + tx] = tile[tx][ty + j];
}

// fused gate + combine with split gate logits:
// a1 = u + w1, a2 = u + w2; g = sigmoid(sigmoid(a1)-sigmoid(a2));
// out = g*attn1 + (1-g)*attn2
__global__ void __launch_bounds__(256)
combine_kernel(float* __restrict__ out, const float* __restrict__ u,
               const float* __restrict__ w1, const float* __restrict__ w2,
               const float* __restrict__ A1, const float* __restrict__ A2, int n)
{
    int i = blockIdx.x * 256 + threadIdx.x;
    if (i < n) {
        float uu = u[i];
        float s1 = 1.0f / (1.0f + __expf(-(uu + w1[i])));
        float s2 = 1.0f / (1.0f + __expf(-(uu + w2[i])));
        float g  = 1.0f / (1.0f + __expf(-(s1 - s2)));
        out[i] = g * A1[i] + (1.0f - g) * A2[i];
    }
}

// ===========================================================================
extern "C" void kernel_launch(void* const* d_in, const int* in_sizes, int n_in,
                              void* d_out, int out_size)
{
    const float* sp   = (const float*)d_in[0];
    const float* om1  = (const float*)d_in[1];
    const float* om2  = (const float*)d_in[2];
    const float* q_w  = (const float*)d_in[3];
    const float* q_b  = (const float*)d_in[4];
    const float* k1_w = (const float*)d_in[5];
    const float* k1_b = (const float*)d_in[6];
    const float* k2_w = (const float*)d_in[7];
    const float* k2_b = (const float*)d_in[8];
    const float* v_w  = (const float*)d_in[9];
    const float* v_b  = (const float*)d_in[10];
    const float* c1_w = (const float*)d_in[11];
    const float* c1_b = (const float*)d_in[12];
    float* out = (float*)d_out;

    float* base = nullptr;
    cudaGetSymbolAddress((void**)&base, g_scratch);
    float* u     = base + 0 * NC;
    float* w1    = base + 1 * NC;
    float* w2    = base + 2 * NC;
    float* attn1 = base + 3 * NC;
    float* attn2 = base + 4 * NC;
    float* rsum1 = base + 5 * NC;           // 8192
    float* rsum2 = rsum1 + NROWS;           // 8192
    __half* hb   = (__half*)(base + FLOAT_REGION);
    __half* sph  = hb + 0 * NC;
    __half* om1h = hb + 1 * NC;
    __half* om2h = hb + 2 * NC;
    __half* qh   = hb + 3 * NC;
    __half* k1h  = hb + 4 * NC;
    __half* k2h  = hb + 5 * NC;
    __half* vh   = hb + 6 * NC;
    __half* vTh  = hb + 7 * NC;
    __half* S1   = hb + 8 * NC;             // holds E1 = exp(q k1^T * scale)
    __half* S2   = S1 + S_ELEMS;            // holds E2
    __half* wts  = S2 + S_ELEMS;
    __half* qwh  = wts;
    __half* k1wh = wts + 262144;
    __half* k2wh = wts + 524288;
    __half* vwh  = wts + 786432;
    __half* c1wh = wts + 1572864;           // [512 x 1024] fp16

    cudaFuncSetAttribute(mma_nt_kernel<float>,
                         cudaFuncAttributeMaxDynamicSharedMemorySize, SMEM_GEMM);
    cudaFuncSetAttribute(mma_nt_kernel<__half>,
                         cudaFuncAttributeMaxDynamicSharedMemorySize, SMEM_GEMM);

    const float scale = 0.044194173824159223f;  // 1/sqrt(512)
    const int elemBlocks = (int)((NC + 255) / 256);

    // (0) zero the rowsum accumulators
    zero_kernel<<<(2 * NROWS + 255) / 256, 256>>>(rsum1, 2 * NROWS);

    // (1) fused operand conversion
    convert_all_kernel<<<(CVT_TOTAL + 255) / 256, 256>>>(
        sp, om1, om2, q_w, k1_w, k2_w, v_w, c1_w,
        sph, om1h, om2h, qwh, k1wh, k2wh, vwh, c1wh);

    // (2) q / k1 / k2 projections, one z=3 launch
    {
        GemmBatch bt = {};
        bt.C[0] = qh;  bt.C[1] = k1h; bt.C[2] = k2h;
        bt.A0[0] = sph; bt.A0[1] = om1h; bt.A0[2] = om2h;
        bt.B[0] = qwh; bt.B[1] = k1wh; bt.B[2] = k2wh;
        bt.bias[0] = q_b; bt.bias[1] = k1_b; bt.bias[2] = k2_b;
        mma_nt_kernel<__half><<<dim3(CH / 128, NROWS / 128, 3), 256, SMEM_GEMM>>>(
            bt, CH, 512, 512, 9, 1.0f);
    }

    // (3) v projection (K-concat 1536)
    {
        GemmBatch bt = {};
        bt.C[0] = vh; bt.A0[0] = sph; bt.A1[0] = om1h; bt.A2[0] = om2h;
        bt.B[0] = vwh; bt.bias[0] = v_b;
        mma_nt_kernel<__half><<<dim3(CH / 128, NROWS / 128, 1), 256, SMEM_GEMM>>>(
            bt, CH, 1536, 1536, 9, 1.0f);
    }

    // (4) V transpose
    transpose_h_kernel<<<dim3(CH / 32, NROWS / 32), 256>>>(vTh, vh);

    // (5) E1 = exp(q k1^T * scale), E2 = exp(q k2^T * scale) with row-sum
    //     atomics (z=2, fp16 streaming out) — normalization deferred to PV
    {
        GemmBatch bt = {};
        bt.C[0] = S1; bt.C[1] = S2;
        bt.A0[0] = qh; bt.A0[1] = qh;
        bt.B[0] = k1h; bt.B[1] = k2h;
        bt.rs_out[0] = rsum1; bt.rs_out[1] = rsum2;
        mma_nt_kernel<__half><<<dim3(NROWS / 128, NROWS / 128, 2), 256, SMEM_GEMM>>>(
            bt, NROWS, 512, 512, 9, scale);
    }

    // (6) attn1 = (E1 vT^T)/rowsum1, attn2 = (E2 vT^T)/rowsum2 (z=2, fp32 out)
    {
        GemmBatch bt = {};
        bt.C[0] = attn1; bt.C[1] = attn2;
        bt.A0[0] = S1; bt.A0[1] = S2;
        bt.B[0] = vTh; bt.B[1] = vTh;
        bt.rs_in[0] = rsum1; bt.rs_in[1] = rsum2;
        mma_nt_kernel<float><<<dim3(CH / 128, NROWS / 128, 2), 256, SMEM_GEMM>>>(
            bt, CH, NROWS, NROWS, 13, 1.0f);
    }

    // (7) gate logits, split form: u = sp@Wsp^T (+bias), w1 = om1@Wom^T,
    //     w2 = om2@Wom^T — one z=3 launch, K=512, ldb=1024
    {
        GemmBatch bt = {};
        bt.C[0] = u;  bt.C[1] = w1;  bt.C[2] = w2;
        bt.A0[0] = sph; bt.A0[1] = om1h; bt.A0[2] = om2h;
        bt.B[0] = c1wh; bt.B[1] = c1wh + 512; bt.B[2] = c1wh + 512;
        bt.bias[0] = c1_b;
        mma_nt_kernel<float><<<dim3(CH / 128, NROWS / 128, 3), 256, SMEM_GEMM>>>(
            bt, CH, 512, 1024, 9, 1.0f);
    }

    // (8) fused gate + combine
    combine_kernel<<<elemBlocks, 256>>>(out, u, w1, w2, attn1, attn2, (int)NC);
}

// round 13
// speedup vs baseline: 1.4468x; 1.0298x over previous
#include <cuda_runtime.h>
#include <cuda_fp16.h>
#include <cstdint>

#define NROWS 8192
#define CH    512
#define NC    ((size_t)NROWS * CH)          // 4,194,304
#define S_ELEMS ((size_t)NROWS * NROWS)     // 67,108,864

// float region: u,w1,w2,attn1,attn2 (5*NC) + rowsum (2*8192)
// half  region: sph,om1h,om2h,qh,k1h,k2h,vh,vTh (8*NC), S1,S2 (2*S_ELEMS), weights
#define FLOAT_REGION (5 * NC + 2 * NROWS)
#define HALF_REGION  (8 * NC + 2 * S_ELEMS + 2097152)
__device__ float g_scratch[FLOAT_REGION + HALF_REGION / 2 + 1024];

// ===========================================================================
// helpers
// ===========================================================================
__device__ __forceinline__ uint32_t smem_u32(const void* p) {
    uint32_t a;
    asm("{ .reg .u64 t; cvta.to.shared.u64 t, %1; cvt.u32.u64 %0, t; }"
        : "=r"(a) : "l"(p));
    return a;
}
__device__ __forceinline__ void cp16(uint32_t dst, const void* src) {
    asm volatile("cp.async.cg.shared.global [%0], [%1], 16;" :: "r"(dst), "l"(src));
}
__device__ __forceinline__ void ldmx4(uint32_t* r, uint32_t addr) {
    asm volatile("ldmatrix.sync.aligned.m8n8.x4.shared.b16 {%0,%1,%2,%3}, [%4];"
                 : "=r"(r[0]), "=r"(r[1]), "=r"(r[2]), "=r"(r[3]) : "r"(addr));
}
__device__ __forceinline__ void mma_f16(float* d, const uint32_t* a,
                                        uint32_t b0, uint32_t b1) {
    asm volatile(
        "mma.sync.aligned.m16n8k16.row.col.f32.f16.f16.f32 "
        "{%0,%1,%2,%3}, {%4,%5,%6,%7}, {%8,%9}, {%0,%1,%2,%3};"
        : "+f"(d[0]), "+f"(d[1]), "+f"(d[2]), "+f"(d[3])
        : "r"(a[0]), "r"(a[1]), "r"(a[2]), "r"(a[3]), "r"(b0), "r"(b1));
}
// 16B-chunk swizzle within a 64B row -> conflict-free ldmatrix + cp.async
__device__ __forceinline__ uint32_t sw16(int r, int c) {
    return (uint32_t)((c ^ ((r >> 1) & 3)) * 16);
}

// Up to 3 problem instances selected by blockIdx.z
struct GemmBatch {
    void*         C[3];
    const __half* A0[3];
    const __half* A1[3];     // K-concat segment 2 (nullptr if none)
    const __half* A2[3];     // K-concat segment 3
    const __half* B[3];
    const float*  bias[3];
    float*        rs_out[3]; // fp16 out + exp epilogue + row-sum atomics
    const float*  rs_in[3];  // fp32 out: multiply rows by 1/rs_in[row]
};

// ===========================================================================
// fp16 NT GEMM, tile 128x128, BK=32, 4-stage cp.async, 256 threads
// (8 warps 4m x 2n, per-warp 32x64), 2 CTAs/SM.  (R7 engine, unchanged.)
// Epilogue modes:
//   OutT=half,  rs_out != 0 : C = exp(acc*scale) (fp16), atomicAdd row sums
//   OutT=half,  rs_out == 0 : C = acc*scale + bias (fp16)
//   (both fp16 paths use smem staging + truly coalesced 256B-run streamout)
//   OutT=float, rs_in  != 0 : C = (acc*scale) / rs_in[row]
//   OutT=float, rs_in  == 0 : C = acc*scale + bias
// For S-shaped launches (gridDim.x == 64) CTAs are re-rastered into 8-m-tile
// super-rows so each scheduling wave touches a compact L2 working set.
// ===========================================================================
#define STAGES   4
#define A_TILE_B 8192                  // 128 rows * 64B
#define STAGE_B  16384
#define SMEM_GEMM (STAGES * STAGE_B)   // 65536

template <typename OutT>
__global__ void __launch_bounds__(256, 2)
mma_nt_kernel(GemmBatch bt, int Nfull, int K, int ldb, int seg_shift, float scale)
{
    const int z = blockIdx.z;
    OutT* C           = (OutT*)bt.C[z];
    const __half* A0  = bt.A0[z];
    const __half* A1  = bt.A1[z];
    const __half* A2  = bt.A2[z];
    const __half* B   = bt.B[z];
    const float* bias = bt.bias[z];
    float* rs_out     = bt.rs_out[z];
    const float* rs_in = bt.rs_in[z];

    extern __shared__ char sm[];
    const uint32_t sbase = smem_u32(sm);
    const int tid  = threadIdx.x;
    const int warp = tid >> 5;
    const int lane = tid & 31;
    const int wm   = warp >> 1;          // 0..3
    const int wn   = warp & 1;           // 0..1

    // super-tile rasterization for square (64-wide) S launches
    int bx = blockIdx.x, by = blockIdx.y;
    if (gridDim.x == 64) {
        const int t = by * 64 + bx;
        const int g = t >> 9;            // super-row of 8 m-tiles
        const int r = t & 511;
        by = g * 8 + (r & 7);
        bx = r >> 3;
    }
    const int m0   = by * 128;
    const int n0   = bx * 128;
    const int nch  = K >> 5;
    const int segmask = (1 << seg_shift) - 1;

    const int lr = tid >> 1;
    const int lc0 = (tid & 1) * 2;

    auto issue = [&](int c) {
        const int kb  = c << 5;
        const int seg = kb >> seg_shift;
        const __half* Asrc = (seg == 0) ? A0 : ((seg == 1) ? A1 : A2);
        const __half* ap = Asrc + (((size_t)(m0 + lr)) << seg_shift) + (kb & segmask);
        const __half* bp = B + (size_t)(n0 + lr) * ldb + kb;
        const uint32_t st = sbase + (c % STAGES) * STAGE_B + lr * 64;
#pragma unroll
        for (int j = 0; j < 2; j++) {
            const int ch = lc0 + j;
            cp16(st + sw16(lr, ch), ap + ch * 8);
            cp16(st + A_TILE_B + sw16(lr, ch), bp + ch * 8);
        }
        asm volatile("cp.async.commit_group;" ::: "memory");
    };

    float acc[2][8][4];
#pragma unroll
    for (int mt = 0; mt < 2; mt++)
#pragma unroll
        for (int nt = 0; nt < 8; nt++)
#pragma unroll
            for (int r = 0; r < 4; r++) acc[mt][nt][r] = 0.0f;

    issue(0); issue(1); issue(2);

    const int l15 = lane & 15;
    const int lhi = lane >> 4;
    uint32_t aoff[2][2], boff[4][2];
#pragma unroll
    for (int mt = 0; mt < 2; mt++)
#pragma unroll
        for (int ks = 0; ks < 2; ks++) {
            const int r = wm * 32 + mt * 16 + l15;
            aoff[mt][ks] = (uint32_t)r * 64 + sw16(r, 2 * ks + lhi);
        }
#pragma unroll
    for (int np = 0; np < 4; np++)
#pragma unroll
        for (int ks = 0; ks < 2; ks++) {
            const int r = wn * 64 + np * 16 + l15;
            boff[np][ks] = A_TILE_B + (uint32_t)r * 64 + sw16(r, 2 * ks + lhi);
        }

    for (int c = 0; c < nch; c++) {
        asm volatile("cp.async.wait_group %0;" :: "n"(2) : "memory");
        __syncthreads();
        if (c + 3 < nch) issue(c + 3);
        else asm volatile("cp.async.commit_group;" ::: "memory");

        const uint32_t st = sbase + (c % STAGES) * STAGE_B;

        uint32_t af0[2][4], af1[2][4], bf[4][4];
        ldmx4(af0[0], st + aoff[0][0]);
        ldmx4(af0[1], st + aoff[1][0]);
        ldmx4(af1[0], st + aoff[0][1]);
        ldmx4(af1[1], st + aoff[1][1]);
#pragma unroll
        for (int np = 0; np < 4; np++) ldmx4(bf[np], st + boff[np][0]);
#pragma unroll
        for (int mt = 0; mt < 2; mt++)
#pragma unroll
            for (int np = 0; np < 4; np++) {
                mma_f16(acc[mt][2 * np],     af0[mt], bf[np][0], bf[np][2]);
                mma_f16(acc[mt][2 * np + 1], af0[mt], bf[np][1], bf[np][3]);
            }
#pragma unroll
        for (int np = 0; np < 4; np++) ldmx4(bf[np], st + boff[np][1]);
#pragma unroll
        for (int mt = 0; mt < 2; mt++)
#pragma unroll
            for (int np = 0; np < 4; np++) {
                mma_f16(acc[mt][2 * np],     af1[mt], bf[np][0], bf[np][2]);
                mma_f16(acc[mt][2 * np + 1], af1[mt], bf[np][1], bf[np][3]);
            }
    }

    // ------------------------------ epilogue -------------------------------
    const int frow = lane >> 2;
    const int fcol = lane & 3;
    if constexpr (sizeof(OutT) == 2) {
        const bool do_exp = (rs_out != nullptr);
        __syncthreads();                    // done reading pipeline stages
        __half* sbuf = (__half*)sm;
        float rpart[2][2] = {{0.0f, 0.0f}, {0.0f, 0.0f}};
#pragma unroll
        for (int mt = 0; mt < 2; mt++) {
            const int row = wm * 32 + mt * 16 + frow;
#pragma unroll
            for (int nt = 0; nt < 8; nt++) {
                const int col = n0 + wn * 64 + nt * 8 + fcol * 2;
                const int lcol = wn * 64 + nt * 8 + fcol * 2;
                float x0 = acc[mt][nt][0] * scale;
                float x1 = acc[mt][nt][1] * scale;
                float x2 = acc[mt][nt][2] * scale;
                float x3 = acc[mt][nt][3] * scale;
                if (do_exp) {
                    x0 = __expf(fminf(x0, 11.0f));
                    x1 = __expf(fminf(x1, 11.0f));
                    x2 = __expf(fminf(x2, 11.0f));
                    x3 = __expf(fminf(x3, 11.0f));
                    rpart[mt][0] += x0 + x1;
                    rpart[mt][1] += x2 + x3;
                } else if (bias != nullptr) {
                    float b0 = bias[col], b1 = bias[col + 1];
                    x0 += b0; x1 += b1; x2 += b0; x3 += b1;
                }
                *(__half2*)(sbuf + (size_t)row * 136 + lcol) =
                    __floats2half2_rn(x0, x1);
                *(__half2*)(sbuf + (size_t)(row + 8) * 136 + lcol) =
                    __floats2half2_rn(x2, x3);
            }
        }
        __syncthreads();
        // TRULY coalesced streamout: 16-lane groups write 256B contiguous
        // runs (row = tid>>4 advancing by 16; col = (tid&15)*8 halves).
        const int srow0 = tid >> 4;          // 0..15
        const int scol  = (tid & 15) * 8;    // halves
#pragma unroll
        for (int j = 0; j < 8; j++) {
            const int row = srow0 + j * 16;
            uint4 val = *(const uint4*)(sbuf + (size_t)row * 136 + scol);
            __stcs((uint4*)((__half*)C + (size_t)(m0 + row) * Nfull + n0 + scol),
                   val);
        }
        if (do_exp) {
            // reduce partial row sums across the 4 fcol lanes, then atomicAdd
#pragma unroll
            for (int mt = 0; mt < 2; mt++)
#pragma unroll
                for (int h = 0; h < 2; h++) {
                    float v = rpart[mt][h];
                    v += __shfl_xor_sync(0xffffffff, v, 1);
                    v += __shfl_xor_sync(0xffffffff, v, 2);
                    if (fcol == 0)
                        atomicAdd(&rs_out[m0 + wm * 32 + mt * 16 + h * 8 + frow], v);
                }
        }
    } else {
#pragma unroll
        for (int mt = 0; mt < 2; mt++) {
            const int row = m0 + wm * 32 + mt * 16 + frow;
            float s0 = 1.0f, s1 = 1.0f;
            if (rs_in != nullptr) {
                s0 = 1.0f / rs_in[row];
                s1 = 1.0f / rs_in[row + 8];
            }
#pragma unroll
            for (int nt = 0; nt < 8; nt++) {
                const int col = n0 + wn * 64 + nt * 8 + fcol * 2;
                float b0 = 0.0f, b1 = 0.0f;
                if (bias != nullptr) { b0 = bias[col]; b1 = bias[col + 1]; }
                *(float2*)((float*)C + (size_t)row * Nfull + col) =
                    make_float2(acc[mt][nt][0] * scale * s0 + b0,
                                acc[mt][nt][1] * scale * s0 + b1);
                *(float2*)((float*)C + (size_t)(row + 8) * Nfull + col) =
                    make_float2(acc[mt][nt][2] * scale * s1 + b0,
                                acc[mt][nt][3] * scale * s1 + b1);
            }
        }
    }
}

// ===========================================================================
// zero rowsum accumulators (2 * 8192 floats)
// ===========================================================================
__global__ void __launch_bounds__(256)
zero_kernel(float* __restrict__ p, int n)
{
    int i = blockIdx.x * 256 + threadIdx.x;
    if (i < n) p[i] = 0.0f;
}

// ===========================================================================
// Fused fp32->fp16 conversion for all 8 operands
// ===========================================================================
#define SEG_IN  ((int)(NC / 4))
#define SEG_W5  65536
#define SEG_VW  196608
#define SEG_CW  131072
#define CVT_TOTAL (3 * SEG_IN + 3 * SEG_W5 + SEG_VW + SEG_CW)

__global__ void __launch_bounds__(256)
convert_all_kernel(const float* __restrict__ sp, const float* __restrict__ om1,
                   const float* __restrict__ om2, const float* __restrict__ qw,
                   const float* __restrict__ k1w, const float* __restrict__ k2w,
                   const float* __restrict__ vw, const float* __restrict__ cw,
                   __half* __restrict__ sph, __half* __restrict__ om1h,
                   __half* __restrict__ om2h, __half* __restrict__ qwh,
                   __half* __restrict__ k1wh, __half* __restrict__ k2wh,
                   __half* __restrict__ vwh, __half* __restrict__ cwh)
{
    int i = blockIdx.x * 256 + threadIdx.x;
    if (i >= CVT_TOTAL) return;
    const float* src; __half* dst; int off = i;
    if (off < SEG_IN) { src = sp; dst = sph; }
    else if ((off -= SEG_IN) < SEG_IN) { src = om1; dst = om1h; }
    else if ((off -= SEG_IN) < SEG_IN) { src = om2; dst = om2h; }
    else if ((off -= SEG_IN) < SEG_W5) { src = qw; dst = qwh; }
    else if ((off -= SEG_W5) < SEG_W5) { src = k1w; dst = k1wh; }
    else if ((off -= SEG_W5) < SEG_W5) { src = k2w; dst = k2wh; }
    else if ((off -= SEG_W5) < SEG_VW) { src = vw; dst = vwh; }
    else { off -= SEG_VW; src = cw; dst = cwh; }
    float4 x = ((const float4*)src)[off];
    ((__half2*)dst)[2 * off]     = __floats2half2_rn(x.x, x.y);
    ((__half2*)dst)[2 * off + 1] = __floats2half2_rn(x.z, x.w);
}

__global__ void __launch_bounds__(256)
transpose_h_kernel(__half* __restrict__ out, const __half* __restrict__ in)
{
    __shared__ __half tile[32][34];
    const int tx = threadIdx.x & 31;
    const int ty = threadIdx.x >> 5;
    const int x0 = blockIdx.x * 32;
    const int y0 = blockIdx.y * 32;
#pragma unroll
    for (int j = 0; j < 32; j += 8)
        tile[ty + j][tx] = in[(size_t)(y0 + ty + j) * CH + x0 + tx];
    __syncthreads();
#pragma unroll
    for (int j = 0; j < 32; j += 8)
        out[(size_t)(x0 + ty + j) * NROWS + y0 + tx] = tile[tx][ty + j];
}

// fused gate + combine with split gate logits:
// a1 = u + w1, a2 = u + w2; g = sigmoid(sigmoid(a1)-sigmoid(a2));
// out = g*attn1 + (1-g)*attn2
__global__ void __launch_bounds__(256)
combine_kernel(float* __restrict__ out, const float* __restrict__ u,
               const float* __restrict__ w1, const float* __restrict__ w2,
               const float* __restrict__ A1, const float* __restrict__ A2, int n)
{
    int i = blockIdx.x * 256 + threadIdx.x;
    if (i < n) {
        float uu = u[i];
        float s1 = 1.0f / (1.0f + __expf(-(uu + w1[i])));
        float s2 = 1.0f / (1.0f + __expf(-(uu + w2[i])));
        float g  = 1.0f / (1.0f + __expf(-(s1 - s2)));
        out[i] = g * A1[i] + (1.0f - g) * A2[i];
    }
}

// ===========================================================================
extern "C" void kernel_launch(void* const* d_in, const int* in_sizes, int n_in,
                              void* d_out, int out_size)
{
    const float* sp   = (const float*)d_in[0];
    const float* om1  = (const float*)d_in[1];
    const float* om2  = (const float*)d_in[2];
    const float* q_w  = (const float*)d_in[3];
    const float* q_b  = (const float*)d_in[4];
    const float* k1_w = (const float*)d_in[5];
    const float* k1_b = (const float*)d_in[6];
    const float* k2_w = (const float*)d_in[7];
    const float* k2_b = (const float*)d_in[8];
    const float* v_w  = (const float*)d_in[9];
    const float* v_b  = (const float*)d_in[10];
    const float* c1_w = (const float*)d_in[11];
    const float* c1_b = (const float*)d_in[12];
    float* out = (float*)d_out;

    float* base = nullptr;
    cudaGetSymbolAddress((void**)&base, g_scratch);
    float* u     = base + 0 * NC;
    float* w1    = base + 1 * NC;
    float* w2    = base + 2 * NC;
    float* attn1 = base + 3 * NC;
    float* attn2 = base + 4 * NC;
    float* rsum1 = base + 5 * NC;           // 8192
    float* rsum2 = rsum1 + NROWS;           // 8192
    __half* hb   = (__half*)(base + FLOAT_REGION);
    __half* sph  = hb + 0 * NC;
    __half* om1h = hb + 1 * NC;
    __half* om2h = hb + 2 * NC;
    __half* qh   = hb + 3 * NC;
    __half* k1h  = hb + 4 * NC;
    __half* k2h  = hb + 5 * NC;
    __half* vh   = hb + 6 * NC;
    __half* vTh  = hb + 7 * NC;
    __half* S1   = hb + 8 * NC;             // holds E1 = exp(q k1^T * scale)
    __half* S2   = S1 + S_ELEMS;            // holds E2
    __half* wts  = S2 + S_ELEMS;
    __half* qwh  = wts;
    __half* k1wh = wts + 262144;
    __half* k2wh = wts + 524288;
    __half* vwh  = wts + 786432;
    __half* c1wh = wts + 1572864;           // [512 x 1024] fp16

    cudaFuncSetAttribute(mma_nt_kernel<float>,
                         cudaFuncAttributeMaxDynamicSharedMemorySize, SMEM_GEMM);
    cudaFuncSetAttribute(mma_nt_kernel<__half>,
                         cudaFuncAttributeMaxDynamicSharedMemorySize, SMEM_GEMM);

    const float scale = 0.044194173824159223f;  // 1/sqrt(512)
    const int elemBlocks = (int)((NC + 255) / 256);

    // (1) zero the rowsum accumulators
    zero_kernel<<<(2 * NROWS + 255) / 256, 256>>>(rsum1, 2 * NROWS);

    // (2) fused operand conversion
    convert_all_kernel<<<(CVT_TOTAL + 255) / 256, 256>>>(
        sp, om1, om2, q_w, k1_w, k2_w, v_w, c1_w,
        sph, om1h, om2h, qwh, k1wh, k2wh, vwh, c1wh);

    // (3) q / k1 / k2 projections, one z=3 launch
    {
        GemmBatch bt = {};
        bt.C[0] = qh;  bt.C[1] = k1h; bt.C[2] = k2h;
        bt.A0[0] = sph; bt.A0[1] = om1h; bt.A0[2] = om2h;
        bt.B[0] = qwh; bt.B[1] = k1wh; bt.B[2] = k2wh;
        bt.bias[0] = q_b; bt.bias[1] = k1_b; bt.bias[2] = k2_b;
        mma_nt_kernel<__half><<<dim3(CH / 128, NROWS / 128, 3), 256, SMEM_GEMM>>>(
            bt, CH, 512, 512, 9, 1.0f);
    }

    // (4) v projection (K-concat 1536)
    {
        GemmBatch bt = {};
        bt.C[0] = vh; bt.A0[0] = sph; bt.A1[0] = om1h; bt.A2[0] = om2h;
        bt.B[0] = vwh; bt.bias[0] = v_b;
        mma_nt_kernel<__half><<<dim3(CH / 128, NROWS / 128, 1), 256, SMEM_GEMM>>>(
            bt, CH, 1536, 1536, 9, 1.0f);
    }

    // (5) E1 = exp(q k1^T * scale), rowsum1  (single-z launch)
    {
        GemmBatch bt = {};
        bt.C[0] = S1; bt.A0[0] = qh; bt.B[0] = k1h; bt.rs_out[0] = rsum1;
        mma_nt_kernel<__half><<<dim3(NROWS / 128, NROWS / 128, 1), 256, SMEM_GEMM>>>(
            bt, NROWS, 512, 512, 9, scale);
    }

    // (6) E2 = exp(q k2^T * scale), rowsum2
    {
        GemmBatch bt = {};
        bt.C[0] = S2; bt.A0[0] = qh; bt.B[0] = k2h; bt.rs_out[0] = rsum2;
        mma_nt_kernel<__half><<<dim3(NROWS / 128, NROWS / 128, 1), 256, SMEM_GEMM>>>(
            bt, NROWS, 512, 512, 9, scale);
    }

    // (7) V transpose
    transpose_h_kernel<<<dim3(CH / 32, NROWS / 32), 256>>>(vTh, vh);

    // (8) attn1 = (E1 vT^T)/rowsum1, attn2 = (E2 vT^T)/rowsum2 (z=2, fp32 out)
    {
        GemmBatch bt = {};
        bt.C[0] = attn1; bt.C[1] = attn2;
        bt.A0[0] = S1; bt.A0[1] = S2;
        bt.B[0] = vTh; bt.B[1] = vTh;
        bt.rs_in[0] = rsum1; bt.rs_in[1] = rsum2;
        mma_nt_kernel<float><<<dim3(CH / 128, NROWS / 128, 2), 256, SMEM_GEMM>>>(
            bt, CH, NROWS, NROWS, 13, 1.0f);
    }

    // (9) gate logits, split form: u = sp@Wsp^T (+bias), w1 = om1@Wom^T,
    //     w2 = om2@Wom^T — one z=3 launch, K=512, ldb=1024
    {
        GemmBatch bt = {};
        bt.C[0] = u;  bt.C[1] = w1;  bt.C[2] = w2;
        bt.A0[0] = sph; bt.A0[1] = om1h; bt.A0[2] = om2h;
        bt.B[0] = c1wh; bt.B[1] = c1wh + 512; bt.B[2] = c1wh + 512;
        bt.bias[0] = c1_b;
        mma_nt_kernel<float><<<dim3(CH / 128, NROWS / 128, 3), 256, SMEM_GEMM>>>(
            bt, CH, 512, 1024, 9, 1.0f);
    }

    // (10) fused gate + combine
    combine_kernel<<<elemBlocks, 256>>>(out, u, w1, w2, attn1, attn2, (int)NC);
}

// round 14
// speedup vs baseline: 1.5389x; 1.0637x over previous
#include <cuda_runtime.h>
#include <cuda_fp16.h>
#include <cstdint>

#define NROWS 8192
#define CH    512
#define NC    ((size_t)NROWS * CH)          // 4,194,304
#define S_ELEMS ((size_t)NROWS * NROWS)     // 67,108,864

// float region: u,w1,w2 (3*NC), p0..p3 PV partials (4*NC), rowsum (2*8192)
// half  region: sph,om1h,om2h,qh,k1h,k2h,vh,vTh (8*NC), S1,S2 (2*S_ELEMS), weights
#define FLOAT_REGION (7 * NC + 2 * NROWS)
#define HALF_REGION  (8 * NC + 2 * S_ELEMS + 2097152)
__device__ float g_scratch[FLOAT_REGION + HALF_REGION / 2 + 1024];

// ===========================================================================
// helpers
// ===========================================================================
__device__ __forceinline__ uint32_t smem_u32(const void* p) {
    uint32_t a;
    asm("{ .reg .u64 t; cvta.to.shared.u64 t, %1; cvt.u32.u64 %0, t; }"
        : "=r"(a) : "l"(p));
    return a;
}
__device__ __forceinline__ void cp16(uint32_t dst, const void* src) {
    asm volatile("cp.async.cg.shared.global [%0], [%1], 16;" :: "r"(dst), "l"(src));
}
__device__ __forceinline__ void ldmx4(uint32_t* r, uint32_t addr) {
    asm volatile("ldmatrix.sync.aligned.m8n8.x4.shared.b16 {%0,%1,%2,%3}, [%4];"
                 : "=r"(r[0]), "=r"(r[1]), "=r"(r[2]), "=r"(r[3]) : "r"(addr));
}
__device__ __forceinline__ void mma_f16(float* d, const uint32_t* a,
                                        uint32_t b0, uint32_t b1) {
    asm volatile(
        "mma.sync.aligned.m16n8k16.row.col.f32.f16.f16.f32 "
        "{%0,%1,%2,%3}, {%4,%5,%6,%7}, {%8,%9}, {%0,%1,%2,%3};"
        : "+f"(d[0]), "+f"(d[1]), "+f"(d[2]), "+f"(d[3])
        : "r"(a[0]), "r"(a[1]), "r"(a[2]), "r"(a[3]), "r"(b0), "r"(b1));
}
// 16B-chunk swizzle within a 64B row -> conflict-free ldmatrix + cp.async
__device__ __forceinline__ uint32_t sw16(int r, int c) {
    return (uint32_t)((c ^ ((r >> 1) & 3)) * 16);
}

// Up to 4 problem instances selected by blockIdx.z
struct GemmBatch {
    void*         C[4];
    const __half* A0[4];
    const __half* A1[4];     // K-concat segment 2 (nullptr if none)
    const __half* A2[4];     // K-concat segment 3
    const __half* B[4];
    const float*  bias[4];
    float*        rs_out[4]; // fp16 out + exp epilogue + row-sum atomics
    int           koff[4];   // K-window offset (split-K)
};

// ===========================================================================
// fp16 NT GEMM, tile 128x128, BK=32, 4-stage cp.async, 256 threads
// (8 warps 4m x 2n, per-warp 32x64), 2 CTAs/SM.  (R7 engine, unchanged.)
// K param = K-window length; koff[z] shifts the window (split-K).
// Epilogue modes:
//   OutT=half,  rs_out != 0 : C = exp(acc*scale) (fp16), atomicAdd row sums
//   OutT=half,  rs_out == 0 : C = acc*scale + bias (fp16)
//   (both fp16 paths: smem staging + coalesced 256B-run streaming stores)
//   OutT=float             : C = acc*scale + bias
// For S-shaped launches (gridDim.x == 64) CTAs are re-rastered into 8-m-tile
// super-rows so each scheduling wave touches a compact L2 working set.
// ===========================================================================
#define STAGES   4
#define A_TILE_B 8192                  // 128 rows * 64B
#define STAGE_B  16384
#define SMEM_GEMM (STAGES * STAGE_B)   // 65536

template <typename OutT>
__global__ void __launch_bounds__(256, 2)
mma_nt_kernel(GemmBatch bt, int Nfull, int K, int ldb, int seg_shift, float scale)
{
    const int z = blockIdx.z;
    OutT* C           = (OutT*)bt.C[z];
    const __half* A0  = bt.A0[z];
    const __half* A1  = bt.A1[z];
    const __half* A2  = bt.A2[z];
    const __half* B   = bt.B[z];
    const float* bias = bt.bias[z];
    float* rs_out     = bt.rs_out[z];
    const int koff    = bt.koff[z];

    extern __shared__ char sm[];
    const uint32_t sbase = smem_u32(sm);
    const int tid  = threadIdx.x;
    const int warp = tid >> 5;
    const int lane = tid & 31;
    const int wm   = warp >> 1;          // 0..3
    const int wn   = warp & 1;           // 0..1

    // super-tile rasterization for square (64-wide) S launches
    int bx = blockIdx.x, by = blockIdx.y;
    if (gridDim.x == 64) {
        const int t = by * 64 + bx;
        const int g = t >> 9;            // super-row of 8 m-tiles
        const int r = t & 511;
        by = g * 8 + (r & 7);
        bx = r >> 3;
    }
    const int m0   = by * 128;
    const int n0   = bx * 128;
    const int nch  = K >> 5;
    const int segmask = (1 << seg_shift) - 1;

    const int lr = tid >> 1;
    const int lc0 = (tid & 1) * 2;

    auto issue = [&](int c) {
        const int kb  = (c << 5) + koff;
        const int seg = kb >> seg_shift;
        const __half* Asrc = (seg == 0) ? A0 : ((seg == 1) ? A1 : A2);
        const __half* ap = Asrc + (((size_t)(m0 + lr)) << seg_shift) + (kb & segmask);
        const __half* bp = B + (size_t)(n0 + lr) * ldb + kb;
        const uint32_t st = sbase + (c % STAGES) * STAGE_B + lr * 64;
#pragma unroll
        for (int j = 0; j < 2; j++) {
            const int ch = lc0 + j;
            cp16(st + sw16(lr, ch), ap + ch * 8);
            cp16(st + A_TILE_B + sw16(lr, ch), bp + ch * 8);
        }
        asm volatile("cp.async.commit_group;" ::: "memory");
    };

    float acc[2][8][4];
#pragma unroll
    for (int mt = 0; mt < 2; mt++)
#pragma unroll
        for (int nt = 0; nt < 8; nt++)
#pragma unroll
            for (int r = 0; r < 4; r++) acc[mt][nt][r] = 0.0f;

    issue(0); issue(1); issue(2);

    const int l15 = lane & 15;
    const int lhi = lane >> 4;
    uint32_t aoff[2][2], boff[4][2];
#pragma unroll
    for (int mt = 0; mt < 2; mt++)
#pragma unroll
        for (int ks = 0; ks < 2; ks++) {
            const int r = wm * 32 + mt * 16 + l15;
            aoff[mt][ks] = (uint32_t)r * 64 + sw16(r, 2 * ks + lhi);
        }
#pragma unroll
    for (int np = 0; np < 4; np++)
#pragma unroll
        for (int ks = 0; ks < 2; ks++) {
            const int r = wn * 64 + np * 16 + l15;
            boff[np][ks] = A_TILE_B + (uint32_t)r * 64 + sw16(r, 2 * ks + lhi);
        }

    for (int c = 0; c < nch; c++) {
        asm volatile("cp.async.wait_group %0;" :: "n"(2) : "memory");
        __syncthreads();
        if (c + 3 < nch) issue(c + 3);
        else asm volatile("cp.async.commit_group;" ::: "memory");

        const uint32_t st = sbase + (c % STAGES) * STAGE_B;

        uint32_t af0[2][4], af1[2][4], bf[4][4];
        ldmx4(af0[0], st + aoff[0][0]);
        ldmx4(af0[1], st + aoff[1][0]);
        ldmx4(af1[0], st + aoff[0][1]);
        ldmx4(af1[1], st + aoff[1][1]);
#pragma unroll
        for (int np = 0; np < 4; np++) ldmx4(bf[np], st + boff[np][0]);
#pragma unroll
        for (int mt = 0; mt < 2; mt++)
#pragma unroll
            for (int np = 0; np < 4; np++) {
                mma_f16(acc[mt][2 * np],     af0[mt], bf[np][0], bf[np][2]);
                mma_f16(acc[mt][2 * np + 1], af0[mt], bf[np][1], bf[np][3]);
            }
#pragma unroll
        for (int np = 0; np < 4; np++) ldmx4(bf[np], st + boff[np][1]);
#pragma unroll
        for (int mt = 0; mt < 2; mt++)
#pragma unroll
            for (int np = 0; np < 4; np++) {
                mma_f16(acc[mt][2 * np],     af1[mt], bf[np][0], bf[np][2]);
                mma_f16(acc[mt][2 * np + 1], af1[mt], bf[np][1], bf[np][3]);
            }
    }

    // ------------------------------ epilogue -------------------------------
    const int frow = lane >> 2;
    const int fcol = lane & 3;
    if constexpr (sizeof(OutT) == 2) {
        const bool do_exp = (rs_out != nullptr);
        __syncthreads();                    // done reading pipeline stages
        __half* sbuf = (__half*)sm;
        float rpart[2][2] = {{0.0f, 0.0f}, {0.0f, 0.0f}};
#pragma unroll
        for (int mt = 0; mt < 2; mt++) {
            const int row = wm * 32 + mt * 16 + frow;
#pragma unroll
            for (int nt = 0; nt < 8; nt++) {
                const int col = n0 + wn * 64 + nt * 8 + fcol * 2;
                const int lcol = wn * 64 + nt * 8 + fcol * 2;
                float x0 = acc[mt][nt][0] * scale;
                float x1 = acc[mt][nt][1] * scale;
                float x2 = acc[mt][nt][2] * scale;
                float x3 = acc[mt][nt][3] * scale;
                if (do_exp) {
                    x0 = __expf(fminf(x0, 11.0f));
                    x1 = __expf(fminf(x1, 11.0f));
                    x2 = __expf(fminf(x2, 11.0f));
                    x3 = __expf(fminf(x3, 11.0f));
                    rpart[mt][0] += x0 + x1;
                    rpart[mt][1] += x2 + x3;
                } else if (bias != nullptr) {
                    float b0 = bias[col], b1 = bias[col + 1];
                    x0 += b0; x1 += b1; x2 += b0; x3 += b1;
                }
                *(__half2*)(sbuf + (size_t)row * 136 + lcol) =
                    __floats2half2_rn(x0, x1);
                *(__half2*)(sbuf + (size_t)(row + 8) * 136 + lcol) =
                    __floats2half2_rn(x2, x3);
            }
        }
        __syncthreads();
        // coalesced streamout: 16-lane groups write 256B contiguous runs
        const int srow0 = tid >> 4;          // 0..15
        const int scol  = (tid & 15) * 8;    // halves
#pragma unroll
        for (int j = 0; j < 8; j++) {
            const int row = srow0 + j * 16;
            uint4 val = *(const uint4*)(sbuf + (size_t)row * 136 + scol);
            __stcs((uint4*)((__half*)C + (size_t)(m0 + row) * Nfull + n0 + scol),
                   val);
        }
        if (do_exp) {
#pragma unroll
            for (int mt = 0; mt < 2; mt++)
#pragma unroll
                for (int h = 0; h < 2; h++) {
                    float v = rpart[mt][h];
                    v += __shfl_xor_sync(0xffffffff, v, 1);
                    v += __shfl_xor_sync(0xffffffff, v, 2);
                    if (fcol == 0)
                        atomicAdd(&rs_out[m0 + wm * 32 + mt * 16 + h * 8 + frow], v);
                }
        }
    } else {
#pragma unroll
        for (int mt = 0; mt < 2; mt++) {
            const int row = m0 + wm * 32 + mt * 16 + frow;
#pragma unroll
            for (int nt = 0; nt < 8; nt++) {
                const int col = n0 + wn * 64 + nt * 8 + fcol * 2;
                float b0 = 0.0f, b1 = 0.0f;
                if (bias != nullptr) { b0 = bias[col]; b1 = bias[col + 1]; }
                *(float2*)((float*)C + (size_t)row * Nfull + col) =
                    make_float2(acc[mt][nt][0] * scale + b0,
                                acc[mt][nt][1] * scale + b1);
                *(float2*)((float*)C + (size_t)(row + 8) * Nfull + col) =
                    make_float2(acc[mt][nt][2] * scale + b0,
                                acc[mt][nt][3] * scale + b1);
            }
        }
    }
}

// ===========================================================================
// Fused fp32->fp16 conversion for all 8 operands + rowsum zeroing segment
// ===========================================================================
#define SEG_IN  ((int)(NC / 4))
#define SEG_W5  65536
#define SEG_VW  196608
#define SEG_CW  131072
#define SEG_ZR  ((2 * NROWS) / 4)      // 4096 float4 of zeros (rowsums)
#define CVT_TOTAL (3 * SEG_IN + 3 * SEG_W5 + SEG_VW + SEG_CW + SEG_ZR)

__global__ void __launch_bounds__(256)
convert_all_kernel(const float* __restrict__ sp, const float* __restrict__ om1,
                   const float* __restrict__ om2, const float* __restrict__ qw,
                   const float* __restrict__ k1w, const float* __restrict__ k2w,
                   const float* __restrict__ vw, const float* __restrict__ cw,
                   __half* __restrict__ sph, __half* __restrict__ om1h,
                   __half* __restrict__ om2h, __half* __restrict__ qwh,
                   __half* __restrict__ k1wh, __half* __restrict__ k2wh,
                   __half* __restrict__ vwh, __half* __restrict__ cwh,
                   float* __restrict__ rsum)
{
    int i = blockIdx.x * 256 + threadIdx.x;
    if (i >= CVT_TOTAL) return;
    const float* src; __half* dst; int off = i;
    if (off < SEG_IN) { src = sp; dst = sph; }
    else if ((off -= SEG_IN) < SEG_IN) { src = om1; dst = om1h; }
    else if ((off -= SEG_IN) < SEG_IN) { src = om2; dst = om2h; }
    else if ((off -= SEG_IN) < SEG_W5) { src = qw; dst = qwh; }
    else if ((off -= SEG_W5) < SEG_W5) { src = k1w; dst = k1wh; }
    else if ((off -= SEG_W5) < SEG_W5) { src = k2w; dst = k2wh; }
    else if ((off -= SEG_W5) < SEG_VW) { src = vw; dst = vwh; }
    else if ((off -= SEG_VW) < SEG_CW) { src = cw; dst = cwh; }
    else {
        off -= SEG_CW;
        ((float4*)rsum)[off] = make_float4(0.f, 0.f, 0.f, 0.f);
        return;
    }
    float4 x = ((const float4*)src)[off];
    ((__half2*)dst)[2 * off]     = __floats2half2_rn(x.x, x.y);
    ((__half2*)dst)[2 * off + 1] = __floats2half2_rn(x.z, x.w);
}

__global__ void __launch_bounds__(256)
transpose_h_kernel(__half* __restrict__ out, const __half* __restrict__ in)
{
    __shared__ __half tile[32][34];
    const int tx = threadIdx.x & 31;
    const int ty = threadIdx.x >> 5;
    const int x0 = blockIdx.x * 32;
    const int y0 = blockIdx.y * 32;
#pragma unroll
    for (int j = 0; j < 32; j += 8)
        tile[ty + j][tx] = in[(size_t)(y0 + ty + j) * CH + x0 + tx];
    __syncthreads();
#pragma unroll
    for (int j = 0; j < 32; j += 8)
        out[(size_t)(x0 + ty + j) * NROWS + y0 + tx] = tile[tx][ty + j];
}

// fused gate + split-K reduce + normalize + combine:
// attn1 = (p0+p2)/rs1[row]; attn2 = (p1+p3)/rs2[row];
// a1 = u + w1, a2 = u + w2; g = sigmoid(sigmoid(a1)-sigmoid(a2));
// out = g*attn1 + (1-g)*attn2
__global__ void __launch_bounds__(256)
combine_kernel(float* __restrict__ out, const float* __restrict__ u,
               const float* __restrict__ w1, const float* __restrict__ w2,
               const float* __restrict__ p0, const float* __restrict__ p1,
               const float* __restrict__ p2, const float* __restrict__ p3,
               const float* __restrict__ rs1, const float* __restrict__ rs2,
               int n)
{
    int i = blockIdx.x * 256 + threadIdx.x;
    if (i < n) {
        const int row = i >> 9;              // 512 cols per row
        float uu = u[i];
        float s1 = 1.0f / (1.0f + __expf(-(uu + w1[i])));
        float s2 = 1.0f / (1.0f + __expf(-(uu + w2[i])));
        float g  = 1.0f / (1.0f + __expf(-(s1 - s2)));
        float a1 = (p0[i] + p2[i]) / rs1[row];
        float a2 = (p1[i] + p3[i]) / rs2[row];
        out[i] = g * a1 + (1.0f - g) * a2;
    }
}

// ===========================================================================
extern "C" void kernel_launch(void* const* d_in, const int* in_sizes, int n_in,
                              void* d_out, int out_size)
{
    const float* sp   = (const float*)d_in[0];
    const float* om1  = (const float*)d_in[1];
    const float* om2  = (const float*)d_in[2];
    const float* q_w  = (const float*)d_in[3];
    const float* q_b  = (const float*)d_in[4];
    const float* k1_w = (const float*)d_in[5];
    const float* k1_b = (const float*)d_in[6];
    const float* k2_w = (const float*)d_in[7];
    const float* k2_b = (const float*)d_in[8];
    const float* v_w  = (const float*)d_in[9];
    const float* v_b  = (const float*)d_in[10];
    const float* c1_w = (const float*)d_in[11];
    const float* c1_b = (const float*)d_in[12];
    float* out = (float*)d_out;

    float* base = nullptr;
    cudaGetSymbolAddress((void**)&base, g_scratch);
    float* u     = base + 0 * NC;
    float* w1    = base + 1 * NC;
    float* w2    = base + 2 * NC;
    float* p0    = base + 3 * NC;
    float* p1    = base + 4 * NC;
    float* p2    = base + 5 * NC;
    float* p3    = base + 6 * NC;
    float* rsum1 = base + 7 * NC;           // 8192
    float* rsum2 = rsum1 + NROWS;           // 8192
    __half* hb   = (__half*)(base + FLOAT_REGION);
    __half* sph  = hb + 0 * NC;
    __half* om1h = hb + 1 * NC;
    __half* om2h = hb + 2 * NC;
    __half* qh   = hb + 3 * NC;
    __half* k1h  = hb + 4 * NC;
    __half* k2h  = hb + 5 * NC;
    __half* vh   = hb + 6 * NC;
    __half* vTh  = hb + 7 * NC;
    __half* S1   = hb + 8 * NC;             // holds E1 = exp(q k1^T * scale)
    __half* S2   = S1 + S_ELEMS;            // holds E2
    __half* wts  = S2 + S_ELEMS;
    __half* qwh  = wts;
    __half* k1wh = wts + 262144;
    __half* k2wh = wts + 524288;
    __half* vwh  = wts + 786432;
    __half* c1wh = wts + 1572864;           // [512 x 1024] fp16

    cudaFuncSetAttribute(mma_nt_kernel<float>,
                         cudaFuncAttributeMaxDynamicSharedMemorySize, SMEM_GEMM);
    cudaFuncSetAttribute(mma_nt_kernel<__half>,
                         cudaFuncAttributeMaxDynamicSharedMemorySize, SMEM_GEMM);

    const float scale = 0.044194173824159223f;  // 1/sqrt(512)
    const int elemBlocks = (int)((NC + 255) / 256);

    // (1) fused operand conversion + rowsum zeroing
    convert_all_kernel<<<(CVT_TOTAL + 255) / 256, 256>>>(
        sp, om1, om2, q_w, k1_w, k2_w, v_w, c1_w,
        sph, om1h, om2h, qwh, k1wh, k2wh, vwh, c1wh, rsum1);

    // (2) q / k1 / k2 projections, one z=3 launch
    {
        GemmBatch bt = {};
        bt.C[0] = qh;  bt.C[1] = k1h; bt.C[2] = k2h;
        bt.A0[0] = sph; bt.A0[1] = om1h; bt.A0[2] = om2h;
        bt.B[0] = qwh; bt.B[1] = k1wh; bt.B[2] = k2wh;
        bt.bias[0] = q_b; bt.bias[1] = k1_b; bt.bias[2] = k2_b;
        mma_nt_kernel<__half><<<dim3(CH / 128, NROWS / 128, 3), 256, SMEM_GEMM>>>(
            bt, CH, 512, 512, 9, 1.0f);
    }

    // (3) v projection (K-concat 1536)
    {
        GemmBatch bt = {};
        bt.C[0] = vh; bt.A0[0] = sph; bt.A1[0] = om1h; bt.A2[0] = om2h;
        bt.B[0] = vwh; bt.bias[0] = v_b;
        mma_nt_kernel<__half><<<dim3(CH / 128, NROWS / 128, 1), 256, SMEM_GEMM>>>(
            bt, CH, 1536, 1536, 9, 1.0f);
    }

    // (4) E1 = exp(q k1^T * scale) + rowsum1, E2 likewise (z=2)
    {
        GemmBatch bt = {};
        bt.C[0] = S1; bt.C[1] = S2;
        bt.A0[0] = qh; bt.A0[1] = qh;
        bt.B[0] = k1h; bt.B[1] = k2h;
        bt.rs_out[0] = rsum1; bt.rs_out[1] = rsum2;
        mma_nt_kernel<__half><<<dim3(NROWS / 128, NROWS / 128, 2), 256, SMEM_GEMM>>>(
            bt, NROWS, 512, 512, 9, scale);
    }

    // (5) V transpose
    transpose_h_kernel<<<dim3(CH / 32, NROWS / 32), 256>>>(vTh, vh);

    // (6) PV with split-K=2: z = attn + 2*khalf, K-window 4096 each.
    //     p0 = E1·vT[0:4096], p1 = E2·vT[0:4096],
    //     p2 = E1·vT[4096:], p3 = E2·vT[4096:]  (fp32 partials, no bias)
    {
        GemmBatch bt = {};
        bt.C[0] = p0; bt.C[1] = p1; bt.C[2] = p2; bt.C[3] = p3;
        bt.A0[0] = S1; bt.A0[1] = S2; bt.A0[2] = S1; bt.A0[3] = S2;
        bt.B[0] = vTh; bt.B[1] = vTh; bt.B[2] = vTh; bt.B[3] = vTh;
        bt.koff[0] = 0; bt.koff[1] = 0; bt.koff[2] = 4096; bt.koff[3] = 4096;
        mma_nt_kernel<float><<<dim3(CH / 128, NROWS / 128, 4), 256, SMEM_GEMM>>>(
            bt, CH, 4096, NROWS, 13, 1.0f);
    }

    // (7) gate logits, split form: u = sp@Wsp^T (+bias), w1 = om1@Wom^T,
    //     w2 = om2@Wom^T — one z=3 launch, K=512, ldb=1024
    {
        GemmBatch bt = {};
        bt.C[0] = u;  bt.C[1] = w1;  bt.C[2] = w2;
        bt.A0[0] = sph; bt.A0[1] = om1h; bt.A0[2] = om2h;
        bt.B[0] = c1wh; bt.B[1] = c1wh + 512; bt.B[2] = c1wh + 512;
        bt.bias[0] = c1_b;
        mma_nt_kernel<float><<<dim3(CH / 128, NROWS / 128, 3), 256, SMEM_GEMM>>>(
            bt, CH, 512, 1024, 9, 1.0f);
    }

    // (8) fused gate + split-K reduce + normalize + combine
    combine_kernel<<<elemBlocks, 256>>>(out, u, w1, w2, p0, p1, p2, p3,
                                        rsum1, rsum2, (int)NC);
}

// round 15
// speedup vs baseline: 1.5417x; 1.0018x over previous
#include <cuda_runtime.h>
#include <cuda_fp16.h>
#include <cstdint>

#define NROWS 8192
#define CH    512
#define NC    ((size_t)NROWS * CH)          // 4,194,304
#define S_ELEMS ((size_t)NROWS * NROWS)     // 67,108,864

// float region: u,w1,w2 (3*NC), p0..p3 PV partials (4*NC), rowsum (2*8192)
// half  region: sph,om1h,om2h,qh,k1h,k2h,vh,vTh (8*NC), S1,S2 (2*S_ELEMS), weights
#define FLOAT_REGION (7 * NC + 2 * NROWS)
#define HALF_REGION  (8 * NC + 2 * S_ELEMS + 2097152)
__device__ float g_scratch[FLOAT_REGION + HALF_REGION / 2 + 1024];

// ===========================================================================
// helpers
// ===========================================================================
__device__ __forceinline__ uint32_t smem_u32(const void* p) {
    uint32_t a;
    asm("{ .reg .u64 t; cvta.to.shared.u64 t, %1; cvt.u32.u64 %0, t; }"
        : "=r"(a) : "l"(p));
    return a;
}
__device__ __forceinline__ void cp16(uint32_t dst, const void* src) {
    asm volatile("cp.async.cg.shared.global [%0], [%1], 16;" :: "r"(dst), "l"(src));
}
__device__ __forceinline__ void ldmx4(uint32_t* r, uint32_t addr) {
    asm volatile("ldmatrix.sync.aligned.m8n8.x4.shared.b16 {%0,%1,%2,%3}, [%4];"
                 : "=r"(r[0]), "=r"(r[1]), "=r"(r[2]), "=r"(r[3]) : "r"(addr));
}
__device__ __forceinline__ void mma_f16(float* d, const uint32_t* a,
                                        uint32_t b0, uint32_t b1) {
    asm volatile(
        "mma.sync.aligned.m16n8k16.row.col.f32.f16.f16.f32 "
        "{%0,%1,%2,%3}, {%4,%5,%6,%7}, {%8,%9}, {%0,%1,%2,%3};"
        : "+f"(d[0]), "+f"(d[1]), "+f"(d[2]), "+f"(d[3])
        : "r"(a[0]), "r"(a[1]), "r"(a[2]), "r"(a[3]), "r"(b0), "r"(b1));
}
// 16B-chunk swizzle within a 64B row -> conflict-free ldmatrix + cp.async
__device__ __forceinline__ uint32_t sw16(int r, int c) {
    return (uint32_t)((c ^ ((r >> 1) & 3)) * 16);
}

// Up to 4 problem instances selected by blockIdx.z
struct GemmBatch {
    void*         C[4];
    const __half* A0[4];
    const __half* A1[4];     // K-concat segment 2 (nullptr if none)
    const __half* A2[4];     // K-concat segment 3
    const __half* B[4];
    const float*  bias[4];
    float*        rs_out[4]; // fp16 out + exp epilogue + row-sum atomics
    int           koff[4];   // K-window offset (split-K)
};

// ===========================================================================
// fp16 NT GEMM, tile 128x128, BK=32, 4-stage cp.async, 256 threads
// (8 warps 4m x 2n, per-warp 32x64), 2 CTAs/SM.  (R7 engine, unchanged.)
// K param = K-window length; koff[z] shifts the window (split-K).
// Epilogue modes:
//   OutT=half,  rs_out != 0 : C = exp(acc*scale) (fp16), atomicAdd row sums
//   OutT=half,  rs_out == 0 : C = acc*scale + bias (fp16)
//   (both fp16 paths: smem staging + coalesced 256B-run streaming stores)
//   OutT=float             : C = acc*scale + bias
// For S-shaped launches (gridDim.x == 64) CTAs are re-rastered into 8-m-tile
// super-rows so each scheduling wave touches a compact L2 working set.
// ===========================================================================
#define STAGES   4
#define A_TILE_B 8192                  // 128 rows * 64B
#define STAGE_B  16384
#define SMEM_GEMM (STAGES * STAGE_B)   // 65536

template <typename OutT>
__global__ void __launch_bounds__(256, 2)
mma_nt_kernel(GemmBatch bt, int Nfull, int K, int ldb, int seg_shift, float scale)
{
    const int z = blockIdx.z;
    OutT* C           = (OutT*)bt.C[z];
    const __half* A0  = bt.A0[z];
    const __half* A1  = bt.A1[z];
    const __half* A2  = bt.A2[z];
    const __half* B   = bt.B[z];
    const float* bias = bt.bias[z];
    float* rs_out     = bt.rs_out[z];
    const int koff    = bt.koff[z];

    extern __shared__ char sm[];
    const uint32_t sbase = smem_u32(sm);
    const int tid  = threadIdx.x;
    const int warp = tid >> 5;
    const int lane = tid & 31;
    const int wm   = warp >> 1;          // 0..3
    const int wn   = warp & 1;           // 0..1

    // super-tile rasterization for square (64-wide) S launches
    int bx = blockIdx.x, by = blockIdx.y;
    if (gridDim.x == 64) {
        const int t = by * 64 + bx;
        const int g = t >> 9;            // super-row of 8 m-tiles
        const int r = t & 511;
        by = g * 8 + (r & 7);
        bx = r >> 3;
    }
    const int m0   = by * 128;
    const int n0   = bx * 128;
    const int nch  = K >> 5;
    const int segmask = (1 << seg_shift) - 1;

    const int lr = tid >> 1;
    const int lc0 = (tid & 1) * 2;

    auto issue = [&](int c) {
        const int kb  = (c << 5) + koff;
        const int seg = kb >> seg_shift;
        const __half* Asrc = (seg == 0) ? A0 : ((seg == 1) ? A1 : A2);
        const __half* ap = Asrc + (((size_t)(m0 + lr)) << seg_shift) + (kb & segmask);
        const __half* bp = B + (size_t)(n0 + lr) * ldb + kb;
        const uint32_t st = sbase + (c % STAGES) * STAGE_B + lr * 64;
#pragma unroll
        for (int j = 0; j < 2; j++) {
            const int ch = lc0 + j;
            cp16(st + sw16(lr, ch), ap + ch * 8);
            cp16(st + A_TILE_B + sw16(lr, ch), bp + ch * 8);
        }
        asm volatile("cp.async.commit_group;" ::: "memory");
    };

    float acc[2][8][4];
#pragma unroll
    for (int mt = 0; mt < 2; mt++)
#pragma unroll
        for (int nt = 0; nt < 8; nt++)
#pragma unroll
            for (int r = 0; r < 4; r++) acc[mt][nt][r] = 0.0f;

    issue(0); issue(1); issue(2);

    const int l15 = lane & 15;
    const int lhi = lane >> 4;
    uint32_t aoff[2][2], boff[4][2];
#pragma unroll
    for (int mt = 0; mt < 2; mt++)
#pragma unroll
        for (int ks = 0; ks < 2; ks++) {
            const int r = wm * 32 + mt * 16 + l15;
            aoff[mt][ks] = (uint32_t)r * 64 + sw16(r, 2 * ks + lhi);
        }
#pragma unroll
    for (int np = 0; np < 4; np++)
#pragma unroll
        for (int ks = 0; ks < 2; ks++) {
            const int r = wn * 64 + np * 16 + l15;
            boff[np][ks] = A_TILE_B + (uint32_t)r * 64 + sw16(r, 2 * ks + lhi);
        }

    for (int c = 0; c < nch; c++) {
        asm volatile("cp.async.wait_group %0;" :: "n"(2) : "memory");
        __syncthreads();
        if (c + 3 < nch) issue(c + 3);
        else asm volatile("cp.async.commit_group;" ::: "memory");

        const uint32_t st = sbase + (c % STAGES) * STAGE_B;

        uint32_t af0[2][4], af1[2][4], bf[4][4];
        ldmx4(af0[0], st + aoff[0][0]);
        ldmx4(af0[1], st + aoff[1][0]);
        ldmx4(af1[0], st + aoff[0][1]);
        ldmx4(af1[1], st + aoff[1][1]);
#pragma unroll
        for (int np = 0; np < 4; np++) ldmx4(bf[np], st + boff[np][0]);
#pragma unroll
        for (int mt = 0; mt < 2; mt++)
#pragma unroll
            for (int np = 0; np < 4; np++) {
                mma_f16(acc[mt][2 * np],     af0[mt], bf[np][0], bf[np][2]);
                mma_f16(acc[mt][2 * np + 1], af0[mt], bf[np][1], bf[np][3]);
            }
#pragma unroll
        for (int np = 0; np < 4; np++) ldmx4(bf[np], st + boff[np][1]);
#pragma unroll
        for (int mt = 0; mt < 2; mt++)
#pragma unroll
            for (int np = 0; np < 4; np++) {
                mma_f16(acc[mt][2 * np],     af1[mt], bf[np][0], bf[np][2]);
                mma_f16(acc[mt][2 * np + 1], af1[mt], bf[np][1], bf[np][3]);
            }
    }

    // ------------------------------ epilogue -------------------------------
    const int frow = lane >> 2;
    const int fcol = lane & 3;
    if constexpr (sizeof(OutT) == 2) {
        const bool do_exp = (rs_out != nullptr);
        __syncthreads();                    // done reading pipeline stages
        __half* sbuf = (__half*)sm;
        float rpart[2][2] = {{0.0f, 0.0f}, {0.0f, 0.0f}};
#pragma unroll
        for (int mt = 0; mt < 2; mt++) {
            const int row = wm * 32 + mt * 16 + frow;
#pragma unroll
            for (int nt = 0; nt < 8; nt++) {
                const int col = n0 + wn * 64 + nt * 8 + fcol * 2;
                const int lcol = wn * 64 + nt * 8 + fcol * 2;
                float x0 = acc[mt][nt][0] * scale;
                float x1 = acc[mt][nt][1] * scale;
                float x2 = acc[mt][nt][2] * scale;
                float x3 = acc[mt][nt][3] * scale;
                if (do_exp) {
                    x0 = __expf(fminf(x0, 11.0f));
                    x1 = __expf(fminf(x1, 11.0f));
                    x2 = __expf(fminf(x2, 11.0f));
                    x3 = __expf(fminf(x3, 11.0f));
                    rpart[mt][0] += x0 + x1;
                    rpart[mt][1] += x2 + x3;
                } else if (bias != nullptr) {
                    float b0 = bias[col], b1 = bias[col + 1];
                    x0 += b0; x1 += b1; x2 += b0; x3 += b1;
                }
                *(__half2*)(sbuf + (size_t)row * 136 + lcol) =
                    __floats2half2_rn(x0, x1);
                *(__half2*)(sbuf + (size_t)(row + 8) * 136 + lcol) =
                    __floats2half2_rn(x2, x3);
            }
        }
        __syncthreads();
        // coalesced streamout: 16-lane groups write 256B contiguous runs
        const int srow0 = tid >> 4;          // 0..15
        const int scol  = (tid & 15) * 8;    // halves
#pragma unroll
        for (int j = 0; j < 8; j++) {
            const int row = srow0 + j * 16;
            uint4 val = *(const uint4*)(sbuf + (size_t)row * 136 + scol);
            __stcs((uint4*)((__half*)C + (size_t)(m0 + row) * Nfull + n0 + scol),
                   val);
        }
        if (do_exp) {
#pragma unroll
            for (int mt = 0; mt < 2; mt++)
#pragma unroll
                for (int h = 0; h < 2; h++) {
                    float v = rpart[mt][h];
                    v += __shfl_xor_sync(0xffffffff, v, 1);
                    v += __shfl_xor_sync(0xffffffff, v, 2);
                    if (fcol == 0)
                        atomicAdd(&rs_out[m0 + wm * 32 + mt * 16 + h * 8 + frow], v);
                }
        }
    } else {
#pragma unroll
        for (int mt = 0; mt < 2; mt++) {
            const int row = m0 + wm * 32 + mt * 16 + frow;
#pragma unroll
            for (int nt = 0; nt < 8; nt++) {
                const int col = n0 + wn * 64 + nt * 8 + fcol * 2;
                float b0 = 0.0f, b1 = 0.0f;
                if (bias != nullptr) { b0 = bias[col]; b1 = bias[col + 1]; }
                *(float2*)((float*)C + (size_t)row * Nfull + col) =
                    make_float2(acc[mt][nt][0] * scale + b0,
                                acc[mt][nt][1] * scale + b1);
                *(float2*)((float*)C + (size_t)(row + 8) * Nfull + col) =
                    make_float2(acc[mt][nt][2] * scale + b0,
                                acc[mt][nt][3] * scale + b1);
            }
        }
    }
}

// ===========================================================================
// Fused fp32->fp16 conversion for all 8 operands + rowsum zeroing segment
// ===========================================================================
#define SEG_IN  ((int)(NC / 4))
#define SEG_W5  65536
#define SEG_VW  196608
#define SEG_CW  131072
#define SEG_ZR  ((2 * NROWS) / 4)      // 4096 float4 of zeros (rowsums)
#define CVT_TOTAL (3 * SEG_IN + 3 * SEG_W5 + SEG_VW + SEG_CW + SEG_ZR)

__global__ void __launch_bounds__(256)
convert_all_kernel(const float* __restrict__ sp, const float* __restrict__ om1,
                   const float* __restrict__ om2, const float* __restrict__ qw,
                   const float* __restrict__ k1w, const float* __restrict__ k2w,
                   const float* __restrict__ vw, const float* __restrict__ cw,
                   __half* __restrict__ sph, __half* __restrict__ om1h,
                   __half* __restrict__ om2h, __half* __restrict__ qwh,
                   __half* __restrict__ k1wh, __half* __restrict__ k2wh,
                   __half* __restrict__ vwh, __half* __restrict__ cwh,
                   float* __restrict__ rsum)
{
    int i = blockIdx.x * 256 + threadIdx.x;
    if (i >= CVT_TOTAL) return;
    const float* src; __half* dst; int off = i;
    if (off < SEG_IN) { src = sp; dst = sph; }
    else if ((off -= SEG_IN) < SEG_IN) { src = om1; dst = om1h; }
    else if ((off -= SEG_IN) < SEG_IN) { src = om2; dst = om2h; }
    else if ((off -= SEG_IN) < SEG_W5) { src = qw; dst = qwh; }
    else if ((off -= SEG_W5) < SEG_W5) { src = k1w; dst = k1wh; }
    else if ((off -= SEG_W5) < SEG_W5) { src = k2w; dst = k2wh; }
    else if ((off -= SEG_W5) < SEG_VW) { src = vw; dst = vwh; }
    else if ((off -= SEG_VW) < SEG_CW) { src = cw; dst = cwh; }
    else {
        off -= SEG_CW;
        ((float4*)rsum)[off] = make_float4(0.f, 0.f, 0.f, 0.f);
        return;
    }
    float4 x = ((const float4*)src)[off];
    ((__half2*)dst)[2 * off]     = __floats2half2_rn(x.x, x.y);
    ((__half2*)dst)[2 * off + 1] = __floats2half2_rn(x.z, x.w);
}

__global__ void __launch_bounds__(256)
transpose_h_kernel(__half* __restrict__ out, const __half* __restrict__ in)
{
    __shared__ __half tile[32][34];
    const int tx = threadIdx.x & 31;
    const int ty = threadIdx.x >> 5;
    const int x0 = blockIdx.x * 32;
    const int y0 = blockIdx.y * 32;
#pragma unroll
    for (int j = 0; j < 32; j += 8)
        tile[ty + j][tx] = in[(size_t)(y0 + ty + j) * CH + x0 + tx];
    __syncthreads();
#pragma unroll
    for (int j = 0; j < 32; j += 8)
        out[(size_t)(x0 + ty + j) * NROWS + y0 + tx] = tile[tx][ty + j];
}

// fused gate + split-K reduce + normalize + combine:
// attn1 = (p0+p2)/rs1[row]; attn2 = (p1+p3)/rs2[row];
// a1 = u + w1, a2 = u + w2; g = sigmoid(sigmoid(a1)-sigmoid(a2));
// out = g*attn1 + (1-g)*attn2
__global__ void __launch_bounds__(256)
combine_kernel(float* __restrict__ out, const float* __restrict__ u,
               const float* __restrict__ w1, const float* __restrict__ w2,
               const float* __restrict__ p0, const float* __restrict__ p1,
               const float* __restrict__ p2, const float* __restrict__ p3,
               const float* __restrict__ rs1, const float* __restrict__ rs2,
               int n)
{
    int i = blockIdx.x * 256 + threadIdx.x;
    if (i < n) {
        const int row = i >> 9;              // 512 cols per row
        float uu = u[i];
        float s1 = 1.0f / (1.0f + __expf(-(uu + w1[i])));
        float s2 = 1.0f / (1.0f + __expf(-(uu + w2[i])));
        float g  = 1.0f / (1.0f + __expf(-(s1 - s2)));
        float a1 = (p0[i] + p2[i]) / rs1[row];
        float a2 = (p1[i] + p3[i]) / rs2[row];
        out[i] = g * a1 + (1.0f - g) * a2;
    }
}

// ===========================================================================
extern "C" void kernel_launch(void* const* d_in, const int* in_sizes, int n_in,
                              void* d_out, int out_size)
{
    const float* sp   = (const float*)d_in[0];
    const float* om1  = (const float*)d_in[1];
    const float* om2  = (const float*)d_in[2];
    const float* q_w  = (const float*)d_in[3];
    const float* q_b  = (const float*)d_in[4];
    const float* k1_w = (const float*)d_in[5];
    const float* k1_b = (const float*)d_in[6];
    const float* k2_w = (const float*)d_in[7];
    const float* k2_b = (const float*)d_in[8];
    const float* v_w  = (const float*)d_in[9];
    const float* v_b  = (const float*)d_in[10];
    const float* c1_w = (const float*)d_in[11];
    const float* c1_b = (const float*)d_in[12];
    float* out = (float*)d_out;

    float* base = nullptr;
    cudaGetSymbolAddress((void**)&base, g_scratch);
    float* u     = base + 0 * NC;
    float* w1    = base + 1 * NC;
    float* w2    = base + 2 * NC;
    float* p0    = base + 3 * NC;
    float* p1    = base + 4 * NC;
    float* p2    = base + 5 * NC;
    float* p3    = base + 6 * NC;
    float* rsum1 = base + 7 * NC;           // 8192
    float* rsum2 = rsum1 + NROWS;           // 8192
    __half* hb   = (__half*)(base + FLOAT_REGION);
    __half* sph  = hb + 0 * NC;
    __half* om1h = hb + 1 * NC;
    __half* om2h = hb + 2 * NC;
    __half* qh   = hb + 3 * NC;
    __half* k1h  = hb + 4 * NC;
    __half* k2h  = hb + 5 * NC;
    __half* vh   = hb + 6 * NC;
    __half* vTh  = hb + 7 * NC;
    __half* S1   = hb + 8 * NC;             // holds E1 = exp(q k1^T * scale)
    __half* S2   = S1 + S_ELEMS;            // holds E2
    __half* wts  = S2 + S_ELEMS;
    __half* qwh  = wts;
    __half* k1wh = wts + 262144;
    __half* k2wh = wts + 524288;
    __half* vwh  = wts + 786432;
    __half* c1wh = wts + 1572864;           // [512 x 1024] fp16

    cudaFuncSetAttribute(mma_nt_kernel<float>,
                         cudaFuncAttributeMaxDynamicSharedMemorySize, SMEM_GEMM);
    cudaFuncSetAttribute(mma_nt_kernel<__half>,
                         cudaFuncAttributeMaxDynamicSharedMemorySize, SMEM_GEMM);

    const float scale = 0.044194173824159223f;  // 1/sqrt(512)
    const int elemBlocks = (int)((NC + 255) / 256);

    // (1) fused operand conversion + rowsum zeroing
    convert_all_kernel<<<(CVT_TOTAL + 255) / 256, 256>>>(
        sp, om1, om2, q_w, k1_w, k2_w, v_w, c1_w,
        sph, om1h, om2h, qwh, k1wh, k2wh, vwh, c1wh, rsum1);

    // (2) q / k1 / k2 projections, one z=3 launch
    {
        GemmBatch bt = {};
        bt.C[0] = qh;  bt.C[1] = k1h; bt.C[2] = k2h;
        bt.A0[0] = sph; bt.A0[1] = om1h; bt.A0[2] = om2h;
        bt.B[0] = qwh; bt.B[1] = k1wh; bt.B[2] = k2wh;
        bt.bias[0] = q_b; bt.bias[1] = k1_b; bt.bias[2] = k2_b;
        mma_nt_kernel<__half><<<dim3(CH / 128, NROWS / 128, 3), 256, SMEM_GEMM>>>(
            bt, CH, 512, 512, 9, 1.0f);
    }

    // (3) v projection (K-concat 1536)
    {
        GemmBatch bt = {};
        bt.C[0] = vh; bt.A0[0] = sph; bt.A1[0] = om1h; bt.A2[0] = om2h;
        bt.B[0] = vwh; bt.bias[0] = v_b;
        mma_nt_kernel<__half><<<dim3(CH / 128, NROWS / 128, 1), 256, SMEM_GEMM>>>(
            bt, CH, 1536, 1536, 9, 1.0f);
    }

    // (4) E1 = exp(q k1^T * scale) + rowsum1, E2 likewise (z=2)
    {
        GemmBatch bt = {};
        bt.C[0] = S1; bt.C[1] = S2;
        bt.A0[0] = qh; bt.A0[1] = qh;
        bt.B[0] = k1h; bt.B[1] = k2h;
        bt.rs_out[0] = rsum1; bt.rs_out[1] = rsum2;
        mma_nt_kernel<__half><<<dim3(NROWS / 128, NROWS / 128, 2), 256, SMEM_GEMM>>>(
            bt, NROWS, 512, 512, 9, scale);
    }

    // (5) V transpose
    transpose_h_kernel<<<dim3(CH / 32, NROWS / 32), 256>>>(vTh, vh);

    // (6) PV with split-K=2: z = attn + 2*khalf, K-window 4096 each.
    //     p0 = E1·vT[0:4096], p1 = E2·vT[0:4096],
    //     p2 = E1·vT[4096:], p3 = E2·vT[4096:]  (fp32 partials, no bias)
    {
        GemmBatch bt = {};
        bt.C[0] = p0; bt.C[1] = p1; bt.C[2] = p2; bt.C[3] = p3;
        bt.A0[0] = S1; bt.A0[1] = S2; bt.A0[2] = S1; bt.A0[3] = S2;
        bt.B[0] = vTh; bt.B[1] = vTh; bt.B[2] = vTh; bt.B[3] = vTh;
        bt.koff[0] = 0; bt.koff[1] = 0; bt.koff[2] = 4096; bt.koff[3] = 4096;
        mma_nt_kernel<float><<<dim3(CH / 128, NROWS / 128, 4), 256, SMEM_GEMM>>>(
            bt, CH, 4096, NROWS, 13, 1.0f);
    }

    // (7) gate logits, split form: u = sp@Wsp^T (+bias), w1 = om1@Wom^T,
    //     w2 = om2@Wom^T — one z=3 launch, K=512, ldb=1024
    {
        GemmBatch bt = {};
        bt.C[0] = u;  bt.C[1] = w1;  bt.C[2] = w2;
        bt.A0[0] = sph; bt.A0[1] = om1h; bt.A0[2] = om2h;
        bt.B[0] = c1wh; bt.B[1] = c1wh + 512; bt.B[2] = c1wh + 512;
        bt.bias[0] = c1_b;
        mma_nt_kernel<float><<<dim3(CH / 128, NROWS / 128, 3), 256, SMEM_GEMM>>>(
            bt, CH, 512, 1024, 9, 1.0f);
    }

    // (8) fused gate + split-K reduce + normalize + combine
    combine_kernel<<<elemBlocks, 256>>>(out, u, w1, w2, p0, p1, p2, p3,
                                        rsum1, rsum2, (int)NC);
}